// round 14
// baseline (speedup 1.0000x reference)
#include <cuda_runtime.h>
#include <cuda_fp16.h>
#include <math.h>
#include <stdint.h>

// ---------------- problem dims (fixed) ----------------
#define BATCH   16
#define SEQ     576
#define T_TOK   9216
#define D_IN    1024
#define D_MODEL 2048
#define NEXP    4
#define H_FF    8192
#define CAP     3456
#define ECAP    (NEXP*CAP)      // 13824

#define OUT_COUNTS  (T_TOK*D_MODEL)
#define OUT_EXTRAS_N 9225

// ---------------- scratch ----------------
__device__ float  g_t [(size_t)T_TOK * D_MODEL];
__device__ float  g_probs[(size_t)T_TOK * NEXP];
__device__ float  g_pmax [T_TOK];
__device__ int    g_routes[T_TOK];
__device__ int    g_keep  [T_TOK];
__device__ int    g_slot2tok[ECAP];
__device__ int    g_Mfill[NEXP];
__device__ float  g_counts[NEXP];
__device__ float  g_probsum[NEXP];
__device__ float  g_ndrop[1];
__device__ __half g_xh[(size_t)T_TOK * D_IN];              // 19 MB  ln out hi
__device__ __half g_xl[(size_t)T_TOK * D_IN];              // 19 MB  ln out lo
__device__ __half g_Wph[(size_t)D_IN * D_MODEL];           // 4 MB
__device__ __half g_Wpl[(size_t)D_IN * D_MODEL];           // 4 MB
__device__ __half g_ebh[(size_t)ECAP * D_MODEL];           // 56 MB  gathered tokens fp16
__device__ __half g_hh [(size_t)ECAP * H_FF];              // 226 MB hidden fp16
__device__ __half g_W1h[(size_t)NEXP * D_MODEL * H_FF];    // 134 MB
__device__ __half g_W2h[(size_t)NEXP * H_FF * D_MODEL];    // 134 MB

__device__ __forceinline__ float gelu_exact(float x) {
    return 0.5f * x * (1.0f + erff(x * 0.70710678118654752f));
}
__device__ __forceinline__ uint32_t h2_u32(__half2 h) {
    return *reinterpret_cast<uint32_t*>(&h);
}
__device__ __forceinline__ uint32_t smem_u32(const void* p) {
    uint32_t a;
    asm("{ .reg .u64 t; cvta.to.shared.u64 t, %1; cvt.u32.u64 %0, t; }" : "=r"(a) : "l"(p));
    return a;
}
__device__ __forceinline__ void cp16(uint32_t dst, const void* src) {
    asm volatile("cp.async.cg.shared.global [%0], [%1], 16;" :: "r"(dst), "l"(src) : "memory");
}
__device__ __forceinline__ void cp_commit() { asm volatile("cp.async.commit_group;" ::: "memory"); }
template<int N> __device__ __forceinline__ void cp_wait() {
    asm volatile("cp.async.wait_group %0;" :: "n"(N) : "memory");
}
__device__ __forceinline__ void ldsm4(uint32_t& r0, uint32_t& r1, uint32_t& r2, uint32_t& r3,
                                      uint32_t addr) {
    asm volatile("ldmatrix.sync.aligned.m8n8.x4.shared.b16 {%0,%1,%2,%3}, [%4];"
                 : "=r"(r0), "=r"(r1), "=r"(r2), "=r"(r3) : "r"(addr));
}
__device__ __forceinline__ void ldsm4t(uint32_t& r0, uint32_t& r1, uint32_t& r2, uint32_t& r3,
                                       uint32_t addr) {
    asm volatile("ldmatrix.sync.aligned.m8n8.x4.trans.shared.b16 {%0,%1,%2,%3}, [%4];"
                 : "=r"(r0), "=r"(r1), "=r"(r2), "=r"(r3) : "r"(addr));
}
__device__ __forceinline__ void mma_f16(float& c0, float& c1, float& c2, float& c3,
                                        uint32_t a0, uint32_t a1, uint32_t a2, uint32_t a3,
                                        uint32_t b0, uint32_t b1) {
    asm volatile(
        "mma.sync.aligned.m16n8k16.row.col.f32.f16.f16.f32 "
        "{%0,%1,%2,%3}, {%4,%5,%6,%7}, {%8,%9}, {%0,%1,%2,%3};"
        : "+f"(c0), "+f"(c1), "+f"(c2), "+f"(c3)
        : "r"(a0), "r"(a1), "r"(a2), "r"(a3), "r"(b0), "r"(b1));
}

// ---------------- LayerNorm -> split fp16 hi/lo ----------------
__global__ void ln_kernel(const float* __restrict__ x,
                          const float* __restrict__ g,
                          const float* __restrict__ b)
{
    int tok = blockIdx.x, tid = threadIdx.x;
    const float* xr = x + (size_t)tok * D_IN;
    __shared__ float red[256];
    float s = 0.f;
    for (int i = tid; i < D_IN; i += 256) s += xr[i];
    red[tid] = s; __syncthreads();
    for (int o = 128; o > 0; o >>= 1) { if (tid < o) red[tid] += red[tid + o]; __syncthreads(); }
    float mu = red[0] * (1.0f / D_IN);
    __syncthreads();
    float v = 0.f;
    for (int i = tid; i < D_IN; i += 256) { float d = xr[i] - mu; v += d * d; }
    red[tid] = v; __syncthreads();
    for (int o = 128; o > 0; o >>= 1) { if (tid < o) red[tid] += red[tid + o]; __syncthreads(); }
    float rstd = rsqrtf(red[0] * (1.0f / D_IN) + 1e-5f);
    __half* oh = g_xh + (size_t)tok * D_IN;
    __half* ol = g_xl + (size_t)tok * D_IN;
    for (int i = tid; i < D_IN; i += 256) {
        float xv = (xr[i] - mu) * rstd * g[i] + b[i];
        __half h = __float2half_rn(xv);
        oh[i] = h;
        ol[i] = __float2half_rn(xv - __half2float(h));
    }
}

// ---------------- weight split fp32 -> fp16 hi/lo ----------------
__global__ void split_w(const float* __restrict__ in, __half* __restrict__ oh,
                        __half* __restrict__ ol, size_t n)
{
    size_t i = (size_t)blockIdx.x * blockDim.x + threadIdx.x;
    size_t stride = (size_t)gridDim.x * blockDim.x;
    for (; i < n; i += stride) {
        float v = in[i];
        __half h = __float2half_rn(v);
        oh[i] = h;
        ol[i] = __float2half_rn(v - __half2float(h));
    }
}

// ---------------- weight convert fp32 -> fp16 ----------------
__global__ void convert_w(const float* __restrict__ in, __half* __restrict__ out, size_t n4)
{
    size_t i = (size_t)blockIdx.x * blockDim.x + threadIdx.x;
    size_t stride = (size_t)gridDim.x * blockDim.x;
    const float4* I = reinterpret_cast<const float4*>(in);
    uint2* O = reinterpret_cast<uint2*>(out);
    for (; i < n4; i += stride) {
        float4 v = I[i];
        __half2 lo = __floats2half2_rn(v.x, v.y);
        __half2 hi = __floats2half2_rn(v.z, v.w);
        O[i] = make_uint2(h2_u32(lo), h2_u32(hi));
    }
}

// ---------------- split-fp16 pre-GEMM: g_t = gelu(xn @ pre_W + b), ~fp32 precision ----
// acc = xh*Wh + xh*Wl + xl*Wh  (fp32 accum). M=9216, NT=2048, K=1024.
#define PBM 128
#define PBN 128
#define PBK 32
#define P_AB (PBM * 64)          // 8 KB per A operand per stage
#define P_BB (PBK * 256)         // 8 KB per B operand per stage
#define PSTAGE 3
#define SMEM_PRE (PSTAGE * 2 * (P_AB + P_BB))   // 98304

__global__ void __launch_bounds__(256, 1)
pre_mma(const float* __restrict__ bias)
{
    const int K = D_IN, NT = D_MODEL, C = K / PBK;

    int m0 = blockIdx.x * PBM;
    int n0 = blockIdx.y * PBN;

    extern __shared__ char smem[];
    uint32_t sAh = smem_u32(smem);
    uint32_t sAl = sAh + PSTAGE * P_AB;
    uint32_t sBh = sAl + PSTAGE * P_AB;
    uint32_t sBl = sBh + PSTAGE * P_BB;

    int tid = threadIdx.x;
    int w = tid >> 5, lane = tid & 31;
    int wm = w >> 2, wn = w & 3;
    int g = lane >> 2, tig = lane & 3;
    int l15 = lane & 15, hi = lane >> 4;

    const __half* Ah = g_xh + (size_t)m0 * K;
    const __half* Al = g_xl + (size_t)m0 * K;

    const __half* ah_src[2]; const __half* al_src[2]; uint32_t a_dst[2];
#pragma unroll
    for (int i = 0; i < 2; i++) {
        int idx = i * 256 + tid;
        int row = idx >> 2, kc = idx & 3;
        ah_src[i] = Ah + (size_t)row * K + kc * 8;
        al_src[i] = Al + (size_t)row * K + kc * 8;
        a_dst[i] = (uint32_t)(row * 64 + ((kc ^ ((row >> 1) & 3)) * 16));
    }
    const __half* bh_src[2]; const __half* bl_src[2]; uint32_t b_dst[2];
#pragma unroll
    for (int i = 0; i < 2; i++) {
        int idx = i * 256 + tid;
        int row = idx >> 4, nc = idx & 15;
        bh_src[i] = g_Wph + (size_t)row * NT + n0 + nc * 8;
        bl_src[i] = g_Wpl + (size_t)row * NT + n0 + nc * 8;
        b_dst[i] = (uint32_t)(row * 256 + ((nc ^ (row & 7)) * 16));
    }

    uint32_t offA[4][2];
#pragma unroll
    for (int mt = 0; mt < 4; mt++) {
        int row = wm * 64 + mt * 16 + l15;
        int xr = (row >> 1) & 3;
#pragma unroll
        for (int ks = 0; ks < 2; ks++)
            offA[mt][ks] = (uint32_t)(row * 64 + (((ks * 2 + hi) ^ xr) * 16));
    }
    uint32_t offB[2][2];
#pragma unroll
    for (int ks = 0; ks < 2; ks++) {
        int row = ks * 16 + l15;
#pragma unroll
        for (int p = 0; p < 2; p++) {
            int chunk = wn * 4 + p * 2 + hi;
            offB[ks][p] = (uint32_t)(row * 256 + ((chunk ^ (row & 7)) * 16));
        }
    }

#define PLOAD(c) do {                                                             \
        int s_ = (c) % PSTAGE;                                                    \
        uint32_t ahS = sAh + (uint32_t)(s_ * P_AB);                               \
        uint32_t alS = sAl + (uint32_t)(s_ * P_AB);                               \
        uint32_t bhS = sBh + (uint32_t)(s_ * P_BB);                               \
        uint32_t blS = sBl + (uint32_t)(s_ * P_BB);                               \
        cp16(ahS + a_dst[0], ah_src[0] + (c) * PBK);                              \
        cp16(ahS + a_dst[1], ah_src[1] + (c) * PBK);                              \
        cp16(alS + a_dst[0], al_src[0] + (c) * PBK);                              \
        cp16(alS + a_dst[1], al_src[1] + (c) * PBK);                              \
        cp16(bhS + b_dst[0], bh_src[0] + (size_t)(c) * PBK * NT);                 \
        cp16(bhS + b_dst[1], bh_src[1] + (size_t)(c) * PBK * NT);                 \
        cp16(blS + b_dst[0], bl_src[0] + (size_t)(c) * PBK * NT);                 \
        cp16(blS + b_dst[1], bl_src[1] + (size_t)(c) * PBK * NT);                 \
        cp_commit();                                                              \
    } while (0)

    float acc[4][4][4];
#pragma unroll
    for (int mt = 0; mt < 4; mt++)
#pragma unroll
        for (int nt = 0; nt < 4; nt++)
#pragma unroll
            for (int q = 0; q < 4; q++) acc[mt][nt][q] = 0.f;

    PLOAD(0);
    PLOAD(1);

    for (int c = 0; c < C; c++) {
        cp_wait<1>();
        __syncthreads();
        if (c + 2 < C) PLOAD(c + 2);
        else cp_commit();

        int s = c % PSTAGE;
        uint32_t ahS = sAh + (uint32_t)(s * P_AB);
        uint32_t alS = sAl + (uint32_t)(s * P_AB);
        uint32_t bhS = sBh + (uint32_t)(s * P_BB);
        uint32_t blS = sBl + (uint32_t)(s * P_BB);

#pragma unroll
        for (int ks = 0; ks < 2; ks++) {
            uint32_t ah[4][4], al[4][4];
#pragma unroll
            for (int mt = 0; mt < 4; mt++) {
                ldsm4(ah[mt][0], ah[mt][1], ah[mt][2], ah[mt][3], ahS + offA[mt][ks]);
                ldsm4(al[mt][0], al[mt][1], al[mt][2], al[mt][3], alS + offA[mt][ks]);
            }
            uint32_t bh[2][4], bl[2][4];
#pragma unroll
            for (int p = 0; p < 2; p++) {
                ldsm4t(bh[p][0], bh[p][1], bh[p][2], bh[p][3], bhS + offB[ks][p]);
                ldsm4t(bl[p][0], bl[p][1], bl[p][2], bl[p][3], blS + offB[ks][p]);
            }
#pragma unroll
            for (int mt = 0; mt < 4; mt++)
#pragma unroll
                for (int nt = 0; nt < 4; nt++) {
                    int p = nt >> 1, q = (nt & 1) * 2;
                    mma_f16(acc[mt][nt][0], acc[mt][nt][1], acc[mt][nt][2], acc[mt][nt][3],
                            ah[mt][0], ah[mt][1], ah[mt][2], ah[mt][3],
                            bh[p][q], bh[p][q + 1]);
                    mma_f16(acc[mt][nt][0], acc[mt][nt][1], acc[mt][nt][2], acc[mt][nt][3],
                            ah[mt][0], ah[mt][1], ah[mt][2], ah[mt][3],
                            bl[p][q], bl[p][q + 1]);
                    mma_f16(acc[mt][nt][0], acc[mt][nt][1], acc[mt][nt][2], acc[mt][nt][3],
                            al[mt][0], al[mt][1], al[mt][2], al[mt][3],
                            bh[p][q], bh[p][q + 1]);
                }
        }
    }

    // epilogue: gelu(acc + bias) -> g_t fp32
#pragma unroll
    for (int mt = 0; mt < 4; mt++) {
        int r0 = m0 + wm * 64 + mt * 16 + g;
#pragma unroll
        for (int half = 0; half < 2; half++) {
            int r = r0 + half * 8;
            float* orow = g_t + (size_t)r * D_MODEL + n0;
#pragma unroll
            for (int nt = 0; nt < 4; nt++) {
                int col = wn * 32 + nt * 8 + 2 * tig;
                float v0 = acc[mt][nt][half * 2 + 0] + bias[n0 + col];
                float v1 = acc[mt][nt][half * 2 + 1] + bias[n0 + col + 1];
                float2 o = make_float2(gelu_exact(v0), gelu_exact(v1));
                *reinterpret_cast<float2*>(orow + col) = o;
            }
        }
    }
#undef PLOAD
}

// ---------------- router ----------------
__global__ void router_kernel(const float* __restrict__ swW, const float* __restrict__ swb)
{
    int tok = blockIdx.x, tid = threadIdx.x;
    const float* tr = g_t + (size_t)tok * D_MODEL;
    float a0 = 0.f, a1 = 0.f, a2 = 0.f, a3 = 0.f;
    for (int k = tid; k < D_MODEL; k += 256) {
        float tv = tr[k];
        const float* w = swW + (size_t)k * NEXP;
        a0 += tv * w[0]; a1 += tv * w[1]; a2 += tv * w[2]; a3 += tv * w[3];
    }
    __shared__ float red[4][256];
    red[0][tid] = a0; red[1][tid] = a1; red[2][tid] = a2; red[3][tid] = a3;
    __syncthreads();
    for (int o = 128; o > 0; o >>= 1) {
        if (tid < o) {
            red[0][tid] += red[0][tid + o]; red[1][tid] += red[1][tid + o];
            red[2][tid] += red[2][tid + o]; red[3][tid] += red[3][tid + o];
        }
        __syncthreads();
    }
    if (tid == 0) {
        float l[NEXP]; float mx = -1e30f; int arg = 0;
        for (int e = 0; e < NEXP; e++) {
            l[e] = red[e][0] + swb[e];
            if (l[e] > mx) { mx = l[e]; arg = e; }
        }
        float s = 0.f, p[NEXP];
        for (int e = 0; e < NEXP; e++) { p[e] = expf(l[e] - mx); s += p[e]; }
        float inv = 1.0f / s;
        for (int e = 0; e < NEXP; e++) g_probs[(size_t)tok * NEXP + e] = p[e] * inv;
        g_routes[tok] = arg;
        g_pmax[tok] = inv;
    }
}

__global__ void probsum_kernel()
{
    int e = blockIdx.x, tid = threadIdx.x;
    float s = 0.f;
    for (int t = tid; t < T_TOK; t += 256) s += g_probs[(size_t)t * NEXP + e];
    __shared__ float red[256];
    red[tid] = s; __syncthreads();
    for (int o = 128; o > 0; o >>= 1) { if (tid < o) red[tid] += red[tid + o]; __syncthreads(); }
    if (tid == 0) g_probsum[e] = red[0];
}

// ---------------- capacity scan ----------------
__global__ void scan_kernel()
{
    __shared__ int cnt[256][NEXP];
    int tid = threadIdx.x;
    const int CHUNK = T_TOK / 256;
    int base = tid * CHUNK;
    int c[NEXP] = {0, 0, 0, 0};
    for (int i = 0; i < CHUNK; i++) c[g_routes[base + i]]++;
    for (int e = 0; e < NEXP; e++) cnt[tid][e] = c[e];
    __syncthreads();
    if (tid == 0) {
        int run[NEXP] = {0, 0, 0, 0};
        for (int th = 0; th < 256; th++)
            for (int e = 0; e < NEXP; e++) {
                int tmp = cnt[th][e]; cnt[th][e] = run[e]; run[e] += tmp;
            }
        int nd = 0;
        for (int e = 0; e < NEXP; e++) {
            g_counts[e] = (float)run[e];
            int mf = run[e] < CAP ? run[e] : CAP;
            g_Mfill[e] = mf;
            nd += run[e] - mf;
        }
        g_ndrop[0] = (float)nd;
    }
    __syncthreads();
    int off[NEXP];
    for (int e = 0; e < NEXP; e++) off[e] = cnt[tid][e];
    for (int i = 0; i < CHUNK; i++) {
        int tok = base + i;
        int e = g_routes[tok];
        int p = off[e]++;
        int keep = (p < CAP) ? 1 : 0;
        g_keep[tok] = keep;
        if (keep) g_slot2tok[e * CAP + p] = tok;
    }
}

// ---------------- dispatch gather: g_ebh[slot] = fp16(g_t[tok]) ----------------
__global__ void dispatch_kernel()
{
    int slot = blockIdx.x;
    int e = slot / CAP, p = slot % CAP;
    if (p >= g_Mfill[e]) return;
    int tok = g_slot2tok[slot];
    uint2* dst = reinterpret_cast<uint2*>(g_ebh + (size_t)slot * D_MODEL);
    const float4* src = reinterpret_cast<const float4*>(g_t + (size_t)tok * D_MODEL);
    for (int i = threadIdx.x; i < D_MODEL / 4; i += 128) {
        float4 v = src[i];
        __half2 lo = __floats2half2_rn(v.x, v.y);
        __half2 hi = __floats2half2_rn(v.z, v.w);
        dst[i] = make_uint2(h2_u32(lo), h2_u32(hi));
    }
}

// ---------------- fp16 mma expert GEMMs ----------------
#define BM 128
#define BN 128
#define BK 32
#define A_BYTES (BM * 64)        // 8192
#define B_BYTES (BK * 256)       // 8192
#define NSTAGE 4
#define SMEM_MOE (NSTAGE * (A_BYTES + B_BYTES))   // 65536

// MODE 1: g_hh[slot] = fp16(gelu(g_ebh[slot] @ W1h[e] + b1))   K=2048, NT=8192
// MODE 2: out[tok]   = (g_hh[slot] @ W2h[e] + b2) * pmax        K=8192, NT=2048
template<int MODE>
__global__ void __launch_bounds__(256, 1)
moe_mma(const __half* __restrict__ Wh, const float* __restrict__ bias_all,
        float* __restrict__ out)
{
    const int K  = (MODE == 1) ? D_MODEL : H_FF;
    const int NT = (MODE == 1) ? H_FF : D_MODEL;
    const int C  = K / BK;

    int e = blockIdx.z;
    int mfill = g_Mfill[e];
    int m0 = blockIdx.x * BM;
    if (m0 >= mfill) return;
    int n0 = blockIdx.y * BN;

    extern __shared__ char smem[];
    uint32_t sA = smem_u32(smem);
    uint32_t sB = sA + NSTAGE * A_BYTES;

    int tid = threadIdx.x;
    int w = tid >> 5, lane = tid & 31;
    int wm = w >> 2, wn = w & 3;
    int g = lane >> 2, tig = lane & 3;
    int l15 = lane & 15, hi = lane >> 4;

    const __half* Abase = ((MODE == 1) ? g_ebh : g_hh) + (size_t)(e * CAP + m0) * K;
    const __half* Bbase = Wh + (size_t)e * K * NT;

    const __half* a_src[2]; uint32_t a_dst[2];
#pragma unroll
    for (int i = 0; i < 2; i++) {
        int idx = i * 256 + tid;
        int row = idx >> 2, kc = idx & 3;
        a_src[i] = Abase + (size_t)row * K + kc * 8;
        a_dst[i] = (uint32_t)(row * 64 + ((kc ^ ((row >> 1) & 3)) * 16));
    }
    const __half* b_src[2]; uint32_t b_dst[2];
#pragma unroll
    for (int i = 0; i < 2; i++) {
        int idx = i * 256 + tid;
        int row = idx >> 4, nc = idx & 15;
        b_src[i] = Bbase + (size_t)row * NT + n0 + nc * 8;
        b_dst[i] = (uint32_t)(row * 256 + ((nc ^ (row & 7)) * 16));
    }

    uint32_t offA[4][2];
#pragma unroll
    for (int mt = 0; mt < 4; mt++) {
        int row = wm * 64 + mt * 16 + l15;
        int xr = (row >> 1) & 3;
#pragma unroll
        for (int ks = 0; ks < 2; ks++)
            offA[mt][ks] = (uint32_t)(row * 64 + (((ks * 2 + hi) ^ xr) * 16));
    }
    uint32_t offB[2][2];
#pragma unroll
    for (int ks = 0; ks < 2; ks++) {
        int row = ks * 16 + l15;
#pragma unroll
        for (int p = 0; p < 2; p++) {
            int chunk = wn * 4 + p * 2 + hi;
            offB[ks][p] = (uint32_t)(row * 256 + ((chunk ^ (row & 7)) * 16));
        }
    }

#define LOAD_STAGE(c) do {                                                        \
        int s_ = (c) & (NSTAGE - 1);                                              \
        uint32_t aS = sA + (uint32_t)(s_ * A_BYTES);                              \
        uint32_t bS = sB + (uint32_t)(s_ * B_BYTES);                              \
        cp16(aS + a_dst[0], a_src[0] + (c) * BK);                                 \
        cp16(aS + a_dst[1], a_src[1] + (c) * BK);                                 \
        cp16(bS + b_dst[0], b_src[0] + (size_t)(c) * BK * NT);                    \
        cp16(bS + b_dst[1], b_src[1] + (size_t)(c) * BK * NT);                    \
        cp_commit();                                                              \
    } while (0)

    float acc[4][4][4];
#pragma unroll
    for (int mt = 0; mt < 4; mt++)
#pragma unroll
        for (int nt = 0; nt < 4; nt++)
#pragma unroll
            for (int q = 0; q < 4; q++) acc[mt][nt][q] = 0.f;

    LOAD_STAGE(0);
    LOAD_STAGE(1);
    LOAD_STAGE(2);

    for (int c = 0; c < C; c++) {
        cp_wait<2>();
        __syncthreads();
        if (c + 3 < C) LOAD_STAGE(c + 3);
        else cp_commit();

        int s = c & (NSTAGE - 1);
        uint32_t aS = sA + (uint32_t)(s * A_BYTES);
        uint32_t bS = sB + (uint32_t)(s * B_BYTES);

#pragma unroll
        for (int ks = 0; ks < 2; ks++) {
            uint32_t a[4][4];
#pragma unroll
            for (int mt = 0; mt < 4; mt++)
                ldsm4(a[mt][0], a[mt][1], a[mt][2], a[mt][3], aS + offA[mt][ks]);
            uint32_t b[2][4];
#pragma unroll
            for (int p = 0; p < 2; p++)
                ldsm4t(b[p][0], b[p][1], b[p][2], b[p][3], bS + offB[ks][p]);
#pragma unroll
            for (int mt = 0; mt < 4; mt++)
#pragma unroll
                for (int nt = 0; nt < 4; nt++) {
                    int p = nt >> 1, q = (nt & 1) * 2;
                    mma_f16(acc[mt][nt][0], acc[mt][nt][1], acc[mt][nt][2], acc[mt][nt][3],
                            a[mt][0], a[mt][1], a[mt][2], a[mt][3],
                            b[p][q], b[p][q + 1]);
                }
        }
    }

    // epilogue
    const float* bias = bias_all + (size_t)e * NT + n0;
#pragma unroll
    for (int mt = 0; mt < 4; mt++) {
        int r0 = m0 + wm * 64 + mt * 16 + g;
#pragma unroll
        for (int half = 0; half < 2; half++) {
            int r = r0 + half * 8;
            if (r >= mfill) continue;
#pragma unroll
            for (int nt = 0; nt < 4; nt++) {
                int col = wn * 32 + nt * 8 + 2 * tig;
                float v0 = acc[mt][nt][half * 2 + 0] + bias[col];
                float v1 = acc[mt][nt][half * 2 + 1] + bias[col + 1];
                if (MODE == 1) {
                    __half2 h2 = __floats2half2_rn(gelu_exact(v0), gelu_exact(v1));
                    *reinterpret_cast<uint32_t*>(
                        g_hh + (size_t)(e * CAP + r) * H_FF + n0 + col) = h2_u32(h2);
                } else {
                    int tok = g_slot2tok[e * CAP + r];
                    float pm = g_pmax[tok];
                    float2 o = make_float2(v0 * pm, v1 * pm);
                    *reinterpret_cast<float2*>(out + (size_t)tok * D_MODEL + n0 + col) = o;
                }
            }
        }
    }
#undef LOAD_STAGE
}

// ---------------- dropped tokens ----------------
__global__ void dropped_kernel(float* __restrict__ out)
{
    int tok = blockIdx.x;
    if (g_keep[tok]) return;
    float pm = g_pmax[tok];
    const float* tr = g_t + (size_t)tok * D_MODEL;
    float* orow = out + (size_t)tok * D_MODEL;
    for (int c = threadIdx.x; c < D_MODEL; c += 256) orow[c] = tr[c] * pm;
}

// ---------------- extras ----------------
__global__ void extras_kernel(float* __restrict__ out, int out_size)
{
    int i = blockIdx.x * 256 + threadIdx.x;
    if (i >= OUT_EXTRAS_N) return;
    long long off = (long long)OUT_COUNTS + i;
    if (off >= (long long)out_size) return;
    float v;
    if (i < 4)       v = g_counts[i];
    else if (i < 8)  v = g_probsum[i - 4];
    else if (i == 8) v = g_ndrop[0];
    else             v = g_pmax[i - 9];
    out[off] = v;
}

// ---------------- launch ----------------
extern "C" void kernel_launch(void* const* d_in, const int* in_sizes, int n_in,
                              void* d_out, int out_size)
{
    const float* x     = (const float*)d_in[0];
    const float* ln_g  = (const float*)d_in[1];
    const float* ln_b  = (const float*)d_in[2];
    const float* pre_W = (const float*)d_in[3];
    const float* pre_b = (const float*)d_in[4];
    const float* sw_W  = (const float*)d_in[5];
    const float* sw_b  = (const float*)d_in[6];
    const float* W1    = (const float*)d_in[7];
    const float* b1    = (const float*)d_in[8];
    const float* W2    = (const float*)d_in[9];
    const float* b2    = (const float*)d_in[10];
    float* out = (float*)d_out;

    __half *d_W1h, *d_W2h, *d_Wph, *d_Wpl;
    cudaGetSymbolAddress((void**)&d_W1h, g_W1h);
    cudaGetSymbolAddress((void**)&d_W2h, g_W2h);
    cudaGetSymbolAddress((void**)&d_Wph, g_Wph);
    cudaGetSymbolAddress((void**)&d_Wpl, g_Wpl);
    cudaFuncSetAttribute(moe_mma<1>, cudaFuncAttributeMaxDynamicSharedMemorySize, SMEM_MOE);
    cudaFuncSetAttribute(moe_mma<2>, cudaFuncAttributeMaxDynamicSharedMemorySize, SMEM_MOE);
    cudaFuncSetAttribute(pre_mma, cudaFuncAttributeMaxDynamicSharedMemorySize, SMEM_PRE);

    const size_t WN4 = (size_t)NEXP * D_MODEL * H_FF / 4;

    ln_kernel<<<T_TOK, 256>>>(x, ln_g, ln_b);
    split_w<<<256, 256>>>(pre_W, d_Wph, d_Wpl, (size_t)D_IN * D_MODEL);
    pre_mma<<<dim3(T_TOK / PBM, D_MODEL / PBN), 256, SMEM_PRE>>>(pre_b);
    router_kernel<<<T_TOK, 256>>>(sw_W, sw_b);
    scan_kernel<<<1, 256>>>();
    dispatch_kernel<<<ECAP, 128>>>();
    convert_w<<<2048, 256>>>(W1, d_W1h, WN4);
    convert_w<<<2048, 256>>>(W2, d_W2h, WN4);
    moe_mma<1><<<dim3(CAP / BM, H_FF / BN, NEXP), 256, SMEM_MOE>>>(d_W1h, b1, nullptr);
    moe_mma<2><<<dim3(CAP / BM, D_MODEL / BN, NEXP), 256, SMEM_MOE>>>(d_W2h, b2, out);
    probsum_kernel<<<NEXP, 256>>>();
    dropped_kernel<<<T_TOK, 256>>>(out);
    extras_kernel<<<(OUT_EXTRAS_N + 255) / 256, 256>>>(out, out_size);
}

// round 15
// speedup vs baseline: 1.1188x; 1.1188x over previous
#include <cuda_runtime.h>
#include <cuda_fp16.h>
#include <math.h>
#include <stdint.h>

// ---------------- problem dims (fixed) ----------------
#define BATCH   16
#define SEQ     576
#define T_TOK   9216
#define D_IN    1024
#define D_MODEL 2048
#define NEXP    4
#define H_FF    8192
#define CAP     3456
#define ECAP    (NEXP*CAP)      // 13824

#define OUT_COUNTS  (T_TOK*D_MODEL)
#define OUT_EXTRAS_N 9225

// ---------------- scratch ----------------
__device__ float  g_t [(size_t)T_TOK * D_MODEL];
__device__ float  g_probs[(size_t)T_TOK * NEXP];
__device__ float  g_pmax [T_TOK];
__device__ int    g_routes[T_TOK];
__device__ int    g_keep  [T_TOK];
__device__ int    g_slot2tok[ECAP];
__device__ int    g_Mfill[NEXP];
__device__ float  g_counts[NEXP];
__device__ float  g_probsum[NEXP];
__device__ float  g_ndrop[1];
__device__ __half g_xh[(size_t)T_TOK * D_IN];
__device__ __half g_xl[(size_t)T_TOK * D_IN];
__device__ __half g_Wph[(size_t)D_IN * D_MODEL];
__device__ __half g_Wpl[(size_t)D_IN * D_MODEL];
__device__ __half g_ebh[(size_t)ECAP * D_MODEL];
__device__ __half g_hh [(size_t)ECAP * H_FF];
__device__ __half g_W1h[(size_t)NEXP * D_MODEL * H_FF];
__device__ __half g_W2h[(size_t)NEXP * H_FF * D_MODEL];

__device__ __forceinline__ float gelu_exact(float x) {
    return 0.5f * x * (1.0f + erff(x * 0.70710678118654752f));
}
__device__ __forceinline__ uint32_t h2_u32(__half2 h) {
    return *reinterpret_cast<uint32_t*>(&h);
}
__device__ __forceinline__ uint32_t smem_u32(const void* p) {
    uint32_t a;
    asm("{ .reg .u64 t; cvta.to.shared.u64 t, %1; cvt.u32.u64 %0, t; }" : "=r"(a) : "l"(p));
    return a;
}
__device__ __forceinline__ void cp16(uint32_t dst, const void* src) {
    asm volatile("cp.async.cg.shared.global [%0], [%1], 16;" :: "r"(dst), "l"(src) : "memory");
}
__device__ __forceinline__ void cp_commit() { asm volatile("cp.async.commit_group;" ::: "memory"); }
template<int N> __device__ __forceinline__ void cp_wait() {
    asm volatile("cp.async.wait_group %0;" :: "n"(N) : "memory");
}
__device__ __forceinline__ void ldsm4(uint32_t& r0, uint32_t& r1, uint32_t& r2, uint32_t& r3,
                                      uint32_t addr) {
    asm volatile("ldmatrix.sync.aligned.m8n8.x4.shared.b16 {%0,%1,%2,%3}, [%4];"
                 : "=r"(r0), "=r"(r1), "=r"(r2), "=r"(r3) : "r"(addr));
}
__device__ __forceinline__ void ldsm4t(uint32_t& r0, uint32_t& r1, uint32_t& r2, uint32_t& r3,
                                       uint32_t addr) {
    asm volatile("ldmatrix.sync.aligned.m8n8.x4.trans.shared.b16 {%0,%1,%2,%3}, [%4];"
                 : "=r"(r0), "=r"(r1), "=r"(r2), "=r"(r3) : "r"(addr));
}
__device__ __forceinline__ void mma_f16(float& c0, float& c1, float& c2, float& c3,
                                        uint32_t a0, uint32_t a1, uint32_t a2, uint32_t a3,
                                        uint32_t b0, uint32_t b1) {
    asm volatile(
        "mma.sync.aligned.m16n8k16.row.col.f32.f16.f16.f32 "
        "{%0,%1,%2,%3}, {%4,%5,%6,%7}, {%8,%9}, {%0,%1,%2,%3};"
        : "+f"(c0), "+f"(c1), "+f"(c2), "+f"(c3)
        : "r"(a0), "r"(a1), "r"(a2), "r"(a3), "r"(b0), "r"(b1));
}

// ---------------- LayerNorm -> split fp16 hi/lo ----------------
__global__ void ln_kernel(const float* __restrict__ x,
                          const float* __restrict__ g,
                          const float* __restrict__ b)
{
    int tok = blockIdx.x, tid = threadIdx.x;
    const float* xr = x + (size_t)tok * D_IN;
    __shared__ float red[256];
    float s = 0.f;
    for (int i = tid; i < D_IN; i += 256) s += xr[i];
    red[tid] = s; __syncthreads();
    for (int o = 128; o > 0; o >>= 1) { if (tid < o) red[tid] += red[tid + o]; __syncthreads(); }
    float mu = red[0] * (1.0f / D_IN);
    __syncthreads();
    float v = 0.f;
    for (int i = tid; i < D_IN; i += 256) { float d = xr[i] - mu; v += d * d; }
    red[tid] = v; __syncthreads();
    for (int o = 128; o > 0; o >>= 1) { if (tid < o) red[tid] += red[tid + o]; __syncthreads(); }
    float rstd = rsqrtf(red[0] * (1.0f / D_IN) + 1e-5f);
    __half* oh = g_xh + (size_t)tok * D_IN;
    __half* ol = g_xl + (size_t)tok * D_IN;
    for (int i = tid; i < D_IN; i += 256) {
        float xv = (xr[i] - mu) * rstd * g[i] + b[i];
        __half h = __float2half_rn(xv);
        oh[i] = h;
        ol[i] = __float2half_rn(xv - __half2float(h));
    }
}

// ---------------- weight split fp32 -> fp16 hi/lo ----------------
__global__ void split_w(const float* __restrict__ in, __half* __restrict__ oh,
                        __half* __restrict__ ol, size_t n)
{
    size_t i = (size_t)blockIdx.x * blockDim.x + threadIdx.x;
    size_t stride = (size_t)gridDim.x * blockDim.x;
    for (; i < n; i += stride) {
        float v = in[i];
        __half h = __float2half_rn(v);
        oh[i] = h;
        ol[i] = __float2half_rn(v - __half2float(h));
    }
}

// ---------------- weight convert fp32 -> fp16 ----------------
__global__ void convert_w(const float* __restrict__ in, __half* __restrict__ out, size_t n4)
{
    size_t i = (size_t)blockIdx.x * blockDim.x + threadIdx.x;
    size_t stride = (size_t)gridDim.x * blockDim.x;
    const float4* I = reinterpret_cast<const float4*>(in);
    uint2* O = reinterpret_cast<uint2*>(out);
    for (; i < n4; i += stride) {
        float4 v = I[i];
        __half2 lo = __floats2half2_rn(v.x, v.y);
        __half2 hi = __floats2half2_rn(v.z, v.w);
        O[i] = make_uint2(h2_u32(lo), h2_u32(hi));
    }
}

// ---------------- split-fp16 pre-GEMM ----------------
#define PBM 128
#define PBN 128
#define PBK 32
#define P_AB (PBM * 64)
#define P_BB (PBK * 256)
#define PSTAGE 3
#define SMEM_PRE (PSTAGE * 2 * (P_AB + P_BB))   // 98304

__global__ void __launch_bounds__(256, 1)
pre_mma(const float* __restrict__ bias)
{
    const int K = D_IN, NT = D_MODEL, C = K / PBK;

    int m0 = blockIdx.x * PBM;
    int n0 = blockIdx.y * PBN;

    extern __shared__ char smem[];
    uint32_t sAh = smem_u32(smem);
    uint32_t sAl = sAh + PSTAGE * P_AB;
    uint32_t sBh = sAl + PSTAGE * P_AB;
    uint32_t sBl = sBh + PSTAGE * P_BB;

    int tid = threadIdx.x;
    int w = tid >> 5, lane = tid & 31;
    int wm = w >> 2, wn = w & 3;
    int g = lane >> 2, tig = lane & 3;
    int l15 = lane & 15, hi = lane >> 4;

    const __half* Ah = g_xh + (size_t)m0 * K;
    const __half* Al = g_xl + (size_t)m0 * K;

    const __half* ah_src[2]; const __half* al_src[2]; uint32_t a_dst[2];
#pragma unroll
    for (int i = 0; i < 2; i++) {
        int idx = i * 256 + tid;
        int row = idx >> 2, kc = idx & 3;
        ah_src[i] = Ah + (size_t)row * K + kc * 8;
        al_src[i] = Al + (size_t)row * K + kc * 8;
        a_dst[i] = (uint32_t)(row * 64 + ((kc ^ ((row >> 1) & 3)) * 16));
    }
    const __half* bh_src[2]; const __half* bl_src[2]; uint32_t b_dst[2];
#pragma unroll
    for (int i = 0; i < 2; i++) {
        int idx = i * 256 + tid;
        int row = idx >> 4, nc = idx & 15;
        bh_src[i] = g_Wph + (size_t)row * NT + n0 + nc * 8;
        bl_src[i] = g_Wpl + (size_t)row * NT + n0 + nc * 8;
        b_dst[i] = (uint32_t)(row * 256 + ((nc ^ (row & 7)) * 16));
    }

    uint32_t offA[4][2];
#pragma unroll
    for (int mt = 0; mt < 4; mt++) {
        int row = wm * 64 + mt * 16 + l15;
        int xr = (row >> 1) & 3;
#pragma unroll
        for (int ks = 0; ks < 2; ks++)
            offA[mt][ks] = (uint32_t)(row * 64 + (((ks * 2 + hi) ^ xr) * 16));
    }
    uint32_t offB[2][2];
#pragma unroll
    for (int ks = 0; ks < 2; ks++) {
        int row = ks * 16 + l15;
#pragma unroll
        for (int p = 0; p < 2; p++) {
            int chunk = wn * 4 + p * 2 + hi;
            offB[ks][p] = (uint32_t)(row * 256 + ((chunk ^ (row & 7)) * 16));
        }
    }

#define PLOAD(c) do {                                                             \
        int s_ = (c) % PSTAGE;                                                    \
        uint32_t ahS = sAh + (uint32_t)(s_ * P_AB);                               \
        uint32_t alS = sAl + (uint32_t)(s_ * P_AB);                               \
        uint32_t bhS = sBh + (uint32_t)(s_ * P_BB);                               \
        uint32_t blS = sBl + (uint32_t)(s_ * P_BB);                               \
        cp16(ahS + a_dst[0], ah_src[0] + (c) * PBK);                              \
        cp16(ahS + a_dst[1], ah_src[1] + (c) * PBK);                              \
        cp16(alS + a_dst[0], al_src[0] + (c) * PBK);                              \
        cp16(alS + a_dst[1], al_src[1] + (c) * PBK);                              \
        cp16(bhS + b_dst[0], bh_src[0] + (size_t)(c) * PBK * NT);                 \
        cp16(bhS + b_dst[1], bh_src[1] + (size_t)(c) * PBK * NT);                 \
        cp16(blS + b_dst[0], bl_src[0] + (size_t)(c) * PBK * NT);                 \
        cp16(blS + b_dst[1], bl_src[1] + (size_t)(c) * PBK * NT);                 \
        cp_commit();                                                              \
    } while (0)

    float acc[4][4][4];
#pragma unroll
    for (int mt = 0; mt < 4; mt++)
#pragma unroll
        for (int nt = 0; nt < 4; nt++)
#pragma unroll
            for (int q = 0; q < 4; q++) acc[mt][nt][q] = 0.f;

    PLOAD(0);
    PLOAD(1);

    for (int c = 0; c < C; c++) {
        cp_wait<1>();
        __syncthreads();
        if (c + 2 < C) PLOAD(c + 2);
        else cp_commit();

        int s = c % PSTAGE;
        uint32_t ahS = sAh + (uint32_t)(s * P_AB);
        uint32_t alS = sAl + (uint32_t)(s * P_AB);
        uint32_t bhS = sBh + (uint32_t)(s * P_BB);
        uint32_t blS = sBl + (uint32_t)(s * P_BB);

#pragma unroll
        for (int ks = 0; ks < 2; ks++) {
            uint32_t ah[4][4], al[4][4];
#pragma unroll
            for (int mt = 0; mt < 4; mt++) {
                ldsm4(ah[mt][0], ah[mt][1], ah[mt][2], ah[mt][3], ahS + offA[mt][ks]);
                ldsm4(al[mt][0], al[mt][1], al[mt][2], al[mt][3], alS + offA[mt][ks]);
            }
            uint32_t bh[2][4], bl[2][4];
#pragma unroll
            for (int p = 0; p < 2; p++) {
                ldsm4t(bh[p][0], bh[p][1], bh[p][2], bh[p][3], bhS + offB[ks][p]);
                ldsm4t(bl[p][0], bl[p][1], bl[p][2], bl[p][3], blS + offB[ks][p]);
            }
#pragma unroll
            for (int mt = 0; mt < 4; mt++)
#pragma unroll
                for (int nt = 0; nt < 4; nt++) {
                    int p = nt >> 1, q = (nt & 1) * 2;
                    mma_f16(acc[mt][nt][0], acc[mt][nt][1], acc[mt][nt][2], acc[mt][nt][3],
                            ah[mt][0], ah[mt][1], ah[mt][2], ah[mt][3],
                            bh[p][q], bh[p][q + 1]);
                    mma_f16(acc[mt][nt][0], acc[mt][nt][1], acc[mt][nt][2], acc[mt][nt][3],
                            ah[mt][0], ah[mt][1], ah[mt][2], ah[mt][3],
                            bl[p][q], bl[p][q + 1]);
                    mma_f16(acc[mt][nt][0], acc[mt][nt][1], acc[mt][nt][2], acc[mt][nt][3],
                            al[mt][0], al[mt][1], al[mt][2], al[mt][3],
                            bh[p][q], bh[p][q + 1]);
                }
        }
    }

#pragma unroll
    for (int mt = 0; mt < 4; mt++) {
        int r0 = m0 + wm * 64 + mt * 16 + g;
#pragma unroll
        for (int half = 0; half < 2; half++) {
            int r = r0 + half * 8;
            float* orow = g_t + (size_t)r * D_MODEL + n0;
#pragma unroll
            for (int nt = 0; nt < 4; nt++) {
                int col = wn * 32 + nt * 8 + 2 * tig;
                float v0 = acc[mt][nt][half * 2 + 0] + bias[n0 + col];
                float v1 = acc[mt][nt][half * 2 + 1] + bias[n0 + col + 1];
                float2 o = make_float2(gelu_exact(v0), gelu_exact(v1));
                *reinterpret_cast<float2*>(orow + col) = o;
            }
        }
    }
#undef PLOAD
}

// ---------------- router ----------------
__global__ void router_kernel(const float* __restrict__ swW, const float* __restrict__ swb)
{
    int tok = blockIdx.x, tid = threadIdx.x;
    const float* tr = g_t + (size_t)tok * D_MODEL;
    float a0 = 0.f, a1 = 0.f, a2 = 0.f, a3 = 0.f;
    for (int k = tid; k < D_MODEL; k += 256) {
        float tv = tr[k];
        const float* w = swW + (size_t)k * NEXP;
        a0 += tv * w[0]; a1 += tv * w[1]; a2 += tv * w[2]; a3 += tv * w[3];
    }
    __shared__ float red[4][256];
    red[0][tid] = a0; red[1][tid] = a1; red[2][tid] = a2; red[3][tid] = a3;
    __syncthreads();
    for (int o = 128; o > 0; o >>= 1) {
        if (tid < o) {
            red[0][tid] += red[0][tid + o]; red[1][tid] += red[1][tid + o];
            red[2][tid] += red[2][tid + o]; red[3][tid] += red[3][tid + o];
        }
        __syncthreads();
    }
    if (tid == 0) {
        float l[NEXP]; float mx = -1e30f; int arg = 0;
        for (int e = 0; e < NEXP; e++) {
            l[e] = red[e][0] + swb[e];
            if (l[e] > mx) { mx = l[e]; arg = e; }
        }
        float s = 0.f, p[NEXP];
        for (int e = 0; e < NEXP; e++) { p[e] = expf(l[e] - mx); s += p[e]; }
        float inv = 1.0f / s;
        for (int e = 0; e < NEXP; e++) g_probs[(size_t)tok * NEXP + e] = p[e] * inv;
        g_routes[tok] = arg;
        g_pmax[tok] = inv;
    }
}

__global__ void probsum_kernel()
{
    int e = blockIdx.x, tid = threadIdx.x;
    float s = 0.f;
    for (int t = tid; t < T_TOK; t += 256) s += g_probs[(size_t)t * NEXP + e];
    __shared__ float red[256];
    red[tid] = s; __syncthreads();
    for (int o = 128; o > 0; o >>= 1) { if (tid < o) red[tid] += red[tid + o]; __syncthreads(); }
    if (tid == 0) g_probsum[e] = red[0];
}

// ---------------- capacity scan ----------------
__global__ void scan_kernel()
{
    __shared__ int cnt[256][NEXP];
    int tid = threadIdx.x;
    const int CHUNK = T_TOK / 256;
    int base = tid * CHUNK;
    int c[NEXP] = {0, 0, 0, 0};
    for (int i = 0; i < CHUNK; i++) c[g_routes[base + i]]++;
    for (int e = 0; e < NEXP; e++) cnt[tid][e] = c[e];
    __syncthreads();
    if (tid == 0) {
        int run[NEXP] = {0, 0, 0, 0};
        for (int th = 0; th < 256; th++)
            for (int e = 0; e < NEXP; e++) {
                int tmp = cnt[th][e]; cnt[th][e] = run[e]; run[e] += tmp;
            }
        int nd = 0;
        for (int e = 0; e < NEXP; e++) {
            g_counts[e] = (float)run[e];
            int mf = run[e] < CAP ? run[e] : CAP;
            g_Mfill[e] = mf;
            nd += run[e] - mf;
        }
        g_ndrop[0] = (float)nd;
    }
    __syncthreads();
    int off[NEXP];
    for (int e = 0; e < NEXP; e++) off[e] = cnt[tid][e];
    for (int i = 0; i < CHUNK; i++) {
        int tok = base + i;
        int e = g_routes[tok];
        int p = off[e]++;
        int keep = (p < CAP) ? 1 : 0;
        g_keep[tok] = keep;
        if (keep) g_slot2tok[e * CAP + p] = tok;
    }
}

// ---------------- dispatch gather: g_ebh[slot] = fp16(g_t[tok]) ----------------
__global__ void dispatch_kernel()
{
    int slot = blockIdx.x;
    int e = slot / CAP, p = slot % CAP;
    if (p >= g_Mfill[e]) return;
    int tok = g_slot2tok[slot];
    uint2* dst = reinterpret_cast<uint2*>(g_ebh + (size_t)slot * D_MODEL);
    const float4* src = reinterpret_cast<const float4*>(g_t + (size_t)tok * D_MODEL);
    for (int i = threadIdx.x; i < D_MODEL / 4; i += 128) {
        float4 v = src[i];
        __half2 lo = __floats2half2_rn(v.x, v.y);
        __half2 hi = __floats2half2_rn(v.z, v.w);
        dst[i] = make_uint2(h2_u32(lo), h2_u32(hi));
    }
}

// ---------------- fp16 mma expert GEMMs: CTA tile 128x256, warp tile 64x64 ----------------
#define BM 128
#define BN 256
#define BK 32
#define A_BYTES (BM * 64)        // 8192
#define B_BYTES (BK * 512)       // 16384
#define NSTAGE 4
#define SMEM_MOE (NSTAGE * (A_BYTES + B_BYTES))   // 98304

// MODE 1: g_hh[slot] = fp16(gelu(g_ebh[slot] @ W1h[e] + b1))   K=2048, NT=8192
// MODE 2: out[tok]   = (g_hh[slot] @ W2h[e] + b2) * pmax        K=8192, NT=2048
template<int MODE>
__global__ void __launch_bounds__(256, 1)
moe_mma(const __half* __restrict__ Wh, const float* __restrict__ bias_all,
        float* __restrict__ out)
{
    const int K  = (MODE == 1) ? D_MODEL : H_FF;
    const int NT = (MODE == 1) ? H_FF : D_MODEL;
    const int C  = K / BK;

    int e = blockIdx.z;
    int mfill = g_Mfill[e];
    int m0 = blockIdx.x * BM;
    if (m0 >= mfill) return;
    int n0 = blockIdx.y * BN;

    extern __shared__ char smem[];
    uint32_t sA = smem_u32(smem);
    uint32_t sB = sA + NSTAGE * A_BYTES;

    int tid = threadIdx.x;
    int w = tid >> 5, lane = tid & 31;
    int wm = w >> 2, wn = w & 3;           // warp tile: rows wm*64, cols wn*64
    int g = lane >> 2, tig = lane & 3;
    int l15 = lane & 15, hi = lane >> 4;

    const __half* Abase = ((MODE == 1) ? g_ebh : g_hh) + (size_t)(e * CAP + m0) * K;
    const __half* Bbase = Wh + (size_t)e * K * NT;

    // cp.async: A 2 slots/thread (512 chunks), B 4 slots/thread (1024 chunks)
    const __half* a_src[2]; uint32_t a_dst[2];
#pragma unroll
    for (int i = 0; i < 2; i++) {
        int idx = i * 256 + tid;
        int row = idx >> 2, kc = idx & 3;
        a_src[i] = Abase + (size_t)row * K + kc * 8;
        a_dst[i] = (uint32_t)(row * 64 + ((kc ^ ((row >> 1) & 3)) * 16));
    }
    const __half* b_src[4]; uint32_t b_dst[4];
#pragma unroll
    for (int i = 0; i < 4; i++) {
        int idx = i * 256 + tid;
        int row = idx >> 5, nc = idx & 31;  // 32 chunks per 512B row
        b_src[i] = Bbase + (size_t)row * NT + n0 + nc * 8;
        b_dst[i] = (uint32_t)(row * 512 + ((nc ^ (row & 7)) * 16));
    }

    uint32_t offA[4][2];
#pragma unroll
    for (int mt = 0; mt < 4; mt++) {
        int row = wm * 64 + mt * 16 + l15;
        int xr = (row >> 1) & 3;
#pragma unroll
        for (int ks = 0; ks < 2; ks++)
            offA[mt][ks] = (uint32_t)(row * 64 + (((ks * 2 + hi) ^ xr) * 16));
    }
    uint32_t offB[2][4];
#pragma unroll
    for (int ks = 0; ks < 2; ks++) {
        int row = ks * 16 + l15;
#pragma unroll
        for (int p = 0; p < 4; p++) {
            int chunk = wn * 8 + p * 2 + hi;
            offB[ks][p] = (uint32_t)(row * 512 + ((chunk ^ (row & 7)) * 16));
        }
    }

#define LOAD_STAGE(c) do {                                                        \
        int s_ = (c) & (NSTAGE - 1);                                              \
        uint32_t aS = sA + (uint32_t)(s_ * A_BYTES);                              \
        uint32_t bS = sB + (uint32_t)(s_ * B_BYTES);                              \
        cp16(aS + a_dst[0], a_src[0] + (c) * BK);                                 \
        cp16(aS + a_dst[1], a_src[1] + (c) * BK);                                 \
        cp16(bS + b_dst[0], b_src[0] + (size_t)(c) * BK * NT);                    \
        cp16(bS + b_dst[1], b_src[1] + (size_t)(c) * BK * NT);                    \
        cp16(bS + b_dst[2], b_src[2] + (size_t)(c) * BK * NT);                    \
        cp16(bS + b_dst[3], b_src[3] + (size_t)(c) * BK * NT);                    \
        cp_commit();                                                              \
    } while (0)

    float acc[4][8][4];
#pragma unroll
    for (int mt = 0; mt < 4; mt++)
#pragma unroll
        for (int nt = 0; nt < 8; nt++)
#pragma unroll
            for (int q = 0; q < 4; q++) acc[mt][nt][q] = 0.f;

    LOAD_STAGE(0);
    LOAD_STAGE(1);
    LOAD_STAGE(2);

    for (int c = 0; c < C; c++) {
        cp_wait<2>();
        __syncthreads();
        if (c + 3 < C) LOAD_STAGE(c + 3);
        else cp_commit();

        int s = c & (NSTAGE - 1);
        uint32_t aS = sA + (uint32_t)(s * A_BYTES);
        uint32_t bS = sB + (uint32_t)(s * B_BYTES);

#pragma unroll
        for (int ks = 0; ks < 2; ks++) {
            uint32_t a[4][4];
#pragma unroll
            for (int mt = 0; mt < 4; mt++)
                ldsm4(a[mt][0], a[mt][1], a[mt][2], a[mt][3], aS + offA[mt][ks]);
            uint32_t b[4][4];
#pragma unroll
            for (int p = 0; p < 4; p++)
                ldsm4t(b[p][0], b[p][1], b[p][2], b[p][3], bS + offB[ks][p]);
#pragma unroll
            for (int mt = 0; mt < 4; mt++)
#pragma unroll
                for (int nt = 0; nt < 8; nt++) {
                    int p = nt >> 1, q = (nt & 1) * 2;
                    mma_f16(acc[mt][nt][0], acc[mt][nt][1], acc[mt][nt][2], acc[mt][nt][3],
                            a[mt][0], a[mt][1], a[mt][2], a[mt][3],
                            b[p][q], b[p][q + 1]);
                }
        }
    }

    // epilogue
    const float* bias = bias_all + (size_t)e * NT + n0;
#pragma unroll
    for (int mt = 0; mt < 4; mt++) {
        int r0 = m0 + wm * 64 + mt * 16 + g;
#pragma unroll
        for (int half = 0; half < 2; half++) {
            int r = r0 + half * 8;
            if (r >= mfill) continue;
#pragma unroll
            for (int nt = 0; nt < 8; nt++) {
                int col = wn * 64 + nt * 8 + 2 * tig;
                float v0 = acc[mt][nt][half * 2 + 0] + bias[col];
                float v1 = acc[mt][nt][half * 2 + 1] + bias[col + 1];
                if (MODE == 1) {
                    __half2 h2 = __floats2half2_rn(gelu_exact(v0), gelu_exact(v1));
                    *reinterpret_cast<uint32_t*>(
                        g_hh + (size_t)(e * CAP + r) * H_FF + n0 + col) = h2_u32(h2);
                } else {
                    int tok = g_slot2tok[e * CAP + r];
                    float pm = g_pmax[tok];
                    float2 o = make_float2(v0 * pm, v1 * pm);
                    *reinterpret_cast<float2*>(out + (size_t)tok * D_MODEL + n0 + col) = o;
                }
            }
        }
    }
#undef LOAD_STAGE
}

// ---------------- dropped tokens ----------------
__global__ void dropped_kernel(float* __restrict__ out)
{
    int tok = blockIdx.x;
    if (g_keep[tok]) return;
    float pm = g_pmax[tok];
    const float* tr = g_t + (size_t)tok * D_MODEL;
    float* orow = out + (size_t)tok * D_MODEL;
    for (int c = threadIdx.x; c < D_MODEL; c += 256) orow[c] = tr[c] * pm;
}

// ---------------- extras ----------------
__global__ void extras_kernel(float* __restrict__ out, int out_size)
{
    int i = blockIdx.x * 256 + threadIdx.x;
    if (i >= OUT_EXTRAS_N) return;
    long long off = (long long)OUT_COUNTS + i;
    if (off >= (long long)out_size) return;
    float v;
    if (i < 4)       v = g_counts[i];
    else if (i < 8)  v = g_probsum[i - 4];
    else if (i == 8) v = g_ndrop[0];
    else             v = g_pmax[i - 9];
    out[off] = v;
}

// ---------------- launch ----------------
extern "C" void kernel_launch(void* const* d_in, const int* in_sizes, int n_in,
                              void* d_out, int out_size)
{
    const float* x     = (const float*)d_in[0];
    const float* ln_g  = (const float*)d_in[1];
    const float* ln_b  = (const float*)d_in[2];
    const float* pre_W = (const float*)d_in[3];
    const float* pre_b = (const float*)d_in[4];
    const float* sw_W  = (const float*)d_in[5];
    const float* sw_b  = (const float*)d_in[6];
    const float* W1    = (const float*)d_in[7];
    const float* b1    = (const float*)d_in[8];
    const float* W2    = (const float*)d_in[9];
    const float* b2    = (const float*)d_in[10];
    float* out = (float*)d_out;

    __half *d_W1h, *d_W2h, *d_Wph, *d_Wpl;
    cudaGetSymbolAddress((void**)&d_W1h, g_W1h);
    cudaGetSymbolAddress((void**)&d_W2h, g_W2h);
    cudaGetSymbolAddress((void**)&d_Wph, g_Wph);
    cudaGetSymbolAddress((void**)&d_Wpl, g_Wpl);
    cudaFuncSetAttribute(moe_mma<1>, cudaFuncAttributeMaxDynamicSharedMemorySize, SMEM_MOE);
    cudaFuncSetAttribute(moe_mma<2>, cudaFuncAttributeMaxDynamicSharedMemorySize, SMEM_MOE);
    cudaFuncSetAttribute(pre_mma, cudaFuncAttributeMaxDynamicSharedMemorySize, SMEM_PRE);

    const size_t WN4 = (size_t)NEXP * D_MODEL * H_FF / 4;

    ln_kernel<<<T_TOK, 256>>>(x, ln_g, ln_b);
    split_w<<<256, 256>>>(pre_W, d_Wph, d_Wpl, (size_t)D_IN * D_MODEL);
    pre_mma<<<dim3(T_TOK / PBM, D_MODEL / PBN), 256, SMEM_PRE>>>(pre_b);
    router_kernel<<<T_TOK, 256>>>(sw_W, sw_b);
    scan_kernel<<<1, 256>>>();
    dispatch_kernel<<<ECAP, 128>>>();
    convert_w<<<2048, 256>>>(W1, d_W1h, WN4);
    convert_w<<<2048, 256>>>(W2, d_W2h, WN4);
    moe_mma<1><<<dim3(CAP / BM, H_FF / BN, NEXP), 256, SMEM_MOE>>>(d_W1h, b1, nullptr);
    moe_mma<2><<<dim3(CAP / BM, D_MODEL / BN, NEXP), 256, SMEM_MOE>>>(d_W2h, b2, out);
    probsum_kernel<<<NEXP, 256>>>();
    dropped_kernel<<<T_TOK, 256>>>(out);
    extras_kernel<<<(OUT_EXTRAS_N + 255) / 256, 256>>>(out, out_size);
}

// round 16
// speedup vs baseline: 1.1418x; 1.0206x over previous
#include <cuda_runtime.h>
#include <cuda_fp16.h>
#include <math.h>
#include <stdint.h>

// ---------------- problem dims (fixed) ----------------
#define BATCH   16
#define SEQ     576
#define T_TOK   9216
#define D_IN    1024
#define D_MODEL 2048
#define NEXP    4
#define H_FF    8192
#define CAP     3456
#define ECAP    (NEXP*CAP)      // 13824

#define OUT_COUNTS  (T_TOK*D_MODEL)
#define OUT_EXTRAS_N 9225

// ---------------- scratch ----------------
__device__ float  g_t [(size_t)T_TOK * D_MODEL];
__device__ float  g_probs[(size_t)T_TOK * NEXP];
__device__ float  g_pmax [T_TOK];
__device__ int    g_routes[T_TOK];
__device__ int    g_keep  [T_TOK];
__device__ int    g_slot2tok[ECAP];
__device__ int    g_Mfill[NEXP];
__device__ float  g_counts[NEXP];
__device__ float  g_probsum[NEXP];
__device__ float  g_ndrop[1];
__device__ __half g_xh[(size_t)T_TOK * D_IN];
__device__ __half g_xl[(size_t)T_TOK * D_IN];
__device__ __half g_Wph[(size_t)D_IN * D_MODEL];
__device__ __half g_Wpl[(size_t)D_IN * D_MODEL];
__device__ __half g_ebh[(size_t)ECAP * D_MODEL];
__device__ __half g_hh [(size_t)ECAP * H_FF];
__device__ __half g_W1h[(size_t)NEXP * D_MODEL * H_FF];
__device__ __half g_W2h[(size_t)NEXP * H_FF * D_MODEL];

__device__ __forceinline__ float gelu_exact(float x) {
    return 0.5f * x * (1.0f + erff(x * 0.70710678118654752f));
}
__device__ __forceinline__ uint32_t h2_u32(__half2 h) {
    return *reinterpret_cast<uint32_t*>(&h);
}
__device__ __forceinline__ uint32_t smem_u32(const void* p) {
    uint32_t a;
    asm("{ .reg .u64 t; cvta.to.shared.u64 t, %1; cvt.u32.u64 %0, t; }" : "=r"(a) : "l"(p));
    return a;
}
__device__ __forceinline__ void cp16(uint32_t dst, const void* src) {
    asm volatile("cp.async.cg.shared.global [%0], [%1], 16;" :: "r"(dst), "l"(src) : "memory");
}
__device__ __forceinline__ void cp_commit() { asm volatile("cp.async.commit_group;" ::: "memory"); }
template<int N> __device__ __forceinline__ void cp_wait() {
    asm volatile("cp.async.wait_group %0;" :: "n"(N) : "memory");
}
__device__ __forceinline__ void ldsm4(uint32_t& r0, uint32_t& r1, uint32_t& r2, uint32_t& r3,
                                      uint32_t addr) {
    asm volatile("ldmatrix.sync.aligned.m8n8.x4.shared.b16 {%0,%1,%2,%3}, [%4];"
                 : "=r"(r0), "=r"(r1), "=r"(r2), "=r"(r3) : "r"(addr));
}
__device__ __forceinline__ void ldsm4t(uint32_t& r0, uint32_t& r1, uint32_t& r2, uint32_t& r3,
                                       uint32_t addr) {
    asm volatile("ldmatrix.sync.aligned.m8n8.x4.trans.shared.b16 {%0,%1,%2,%3}, [%4];"
                 : "=r"(r0), "=r"(r1), "=r"(r2), "=r"(r3) : "r"(addr));
}
__device__ __forceinline__ void mma_f16(float& c0, float& c1, float& c2, float& c3,
                                        uint32_t a0, uint32_t a1, uint32_t a2, uint32_t a3,
                                        uint32_t b0, uint32_t b1) {
    asm volatile(
        "mma.sync.aligned.m16n8k16.row.col.f32.f16.f16.f32 "
        "{%0,%1,%2,%3}, {%4,%5,%6,%7}, {%8,%9}, {%0,%1,%2,%3};"
        : "+f"(c0), "+f"(c1), "+f"(c2), "+f"(c3)
        : "r"(a0), "r"(a1), "r"(a2), "r"(a3), "r"(b0), "r"(b1));
}

// ---------------- LayerNorm -> split fp16 hi/lo ----------------
__global__ void ln_kernel(const float* __restrict__ x,
                          const float* __restrict__ g,
                          const float* __restrict__ b)
{
    int tok = blockIdx.x, tid = threadIdx.x;
    const float* xr = x + (size_t)tok * D_IN;
    __shared__ float red[256];
    float s = 0.f;
    for (int i = tid; i < D_IN; i += 256) s += xr[i];
    red[tid] = s; __syncthreads();
    for (int o = 128; o > 0; o >>= 1) { if (tid < o) red[tid] += red[tid + o]; __syncthreads(); }
    float mu = red[0] * (1.0f / D_IN);
    __syncthreads();
    float v = 0.f;
    for (int i = tid; i < D_IN; i += 256) { float d = xr[i] - mu; v += d * d; }
    red[tid] = v; __syncthreads();
    for (int o = 128; o > 0; o >>= 1) { if (tid < o) red[tid] += red[tid + o]; __syncthreads(); }
    float rstd = rsqrtf(red[0] * (1.0f / D_IN) + 1e-5f);
    __half* oh = g_xh + (size_t)tok * D_IN;
    __half* ol = g_xl + (size_t)tok * D_IN;
    for (int i = tid; i < D_IN; i += 256) {
        float xv = (xr[i] - mu) * rstd * g[i] + b[i];
        __half h = __float2half_rn(xv);
        oh[i] = h;
        ol[i] = __float2half_rn(xv - __half2float(h));
    }
}

// ---------------- weight split fp32 -> fp16 hi/lo ----------------
__global__ void split_w(const float* __restrict__ in, __half* __restrict__ oh,
                        __half* __restrict__ ol, size_t n)
{
    size_t i = (size_t)blockIdx.x * blockDim.x + threadIdx.x;
    size_t stride = (size_t)gridDim.x * blockDim.x;
    for (; i < n; i += stride) {
        float v = in[i];
        __half h = __float2half_rn(v);
        oh[i] = h;
        ol[i] = __float2half_rn(v - __half2float(h));
    }
}

// ---------------- weight convert fp32 -> fp16 ----------------
__global__ void convert_w(const float* __restrict__ in, __half* __restrict__ out, size_t n4)
{
    size_t i = (size_t)blockIdx.x * blockDim.x + threadIdx.x;
    size_t stride = (size_t)gridDim.x * blockDim.x;
    const float4* I = reinterpret_cast<const float4*>(in);
    uint2* O = reinterpret_cast<uint2*>(out);
    for (; i < n4; i += stride) {
        float4 v = I[i];
        __half2 lo = __floats2half2_rn(v.x, v.y);
        __half2 hi = __floats2half2_rn(v.z, v.w);
        O[i] = make_uint2(h2_u32(lo), h2_u32(hi));
    }
}

// ---------------- split-fp16 pre-GEMM ----------------
#define PBM 128
#define PBN 128
#define PBK 32
#define P_AB (PBM * 64)
#define P_BB (PBK * 256)
#define PSTAGE 3
#define SMEM_PRE (PSTAGE * 2 * (P_AB + P_BB))   // 98304

__global__ void __launch_bounds__(256, 1)
pre_mma(const float* __restrict__ bias)
{
    const int K = D_IN, NT = D_MODEL, C = K / PBK;

    int m0 = blockIdx.x * PBM;
    int n0 = blockIdx.y * PBN;

    extern __shared__ char smem[];
    uint32_t sAh = smem_u32(smem);
    uint32_t sAl = sAh + PSTAGE * P_AB;
    uint32_t sBh = sAl + PSTAGE * P_AB;
    uint32_t sBl = sBh + PSTAGE * P_BB;

    int tid = threadIdx.x;
    int w = tid >> 5, lane = tid & 31;
    int wm = w >> 2, wn = w & 3;
    int g = lane >> 2, tig = lane & 3;
    int l15 = lane & 15, hi = lane >> 4;

    const __half* Ah = g_xh + (size_t)m0 * K;
    const __half* Al = g_xl + (size_t)m0 * K;

    const __half* ah_src[2]; const __half* al_src[2]; uint32_t a_dst[2];
#pragma unroll
    for (int i = 0; i < 2; i++) {
        int idx = i * 256 + tid;
        int row = idx >> 2, kc = idx & 3;
        ah_src[i] = Ah + (size_t)row * K + kc * 8;
        al_src[i] = Al + (size_t)row * K + kc * 8;
        a_dst[i] = (uint32_t)(row * 64 + ((kc ^ ((row >> 1) & 3)) * 16));
    }
    const __half* bh_src[2]; const __half* bl_src[2]; uint32_t b_dst[2];
#pragma unroll
    for (int i = 0; i < 2; i++) {
        int idx = i * 256 + tid;
        int row = idx >> 4, nc = idx & 15;
        bh_src[i] = g_Wph + (size_t)row * NT + n0 + nc * 8;
        bl_src[i] = g_Wpl + (size_t)row * NT + n0 + nc * 8;
        b_dst[i] = (uint32_t)(row * 256 + ((nc ^ (row & 7)) * 16));
    }

    uint32_t offA[4][2];
#pragma unroll
    for (int mt = 0; mt < 4; mt++) {
        int row = wm * 64 + mt * 16 + l15;
        int xr = (row >> 1) & 3;
#pragma unroll
        for (int ks = 0; ks < 2; ks++)
            offA[mt][ks] = (uint32_t)(row * 64 + (((ks * 2 + hi) ^ xr) * 16));
    }
    uint32_t offB[2][2];
#pragma unroll
    for (int ks = 0; ks < 2; ks++) {
        int row = ks * 16 + l15;
#pragma unroll
        for (int p = 0; p < 2; p++) {
            int chunk = wn * 4 + p * 2 + hi;
            offB[ks][p] = (uint32_t)(row * 256 + ((chunk ^ (row & 7)) * 16));
        }
    }

#define PLOAD(c) do {                                                             \
        int s_ = (c) % PSTAGE;                                                    \
        uint32_t ahS = sAh + (uint32_t)(s_ * P_AB);                               \
        uint32_t alS = sAl + (uint32_t)(s_ * P_AB);                               \
        uint32_t bhS = sBh + (uint32_t)(s_ * P_BB);                               \
        uint32_t blS = sBl + (uint32_t)(s_ * P_BB);                               \
        cp16(ahS + a_dst[0], ah_src[0] + (c) * PBK);                              \
        cp16(ahS + a_dst[1], ah_src[1] + (c) * PBK);                              \
        cp16(alS + a_dst[0], al_src[0] + (c) * PBK);                              \
        cp16(alS + a_dst[1], al_src[1] + (c) * PBK);                              \
        cp16(bhS + b_dst[0], bh_src[0] + (size_t)(c) * PBK * NT);                 \
        cp16(bhS + b_dst[1], bh_src[1] + (size_t)(c) * PBK * NT);                 \
        cp16(blS + b_dst[0], bl_src[0] + (size_t)(c) * PBK * NT);                 \
        cp16(blS + b_dst[1], bl_src[1] + (size_t)(c) * PBK * NT);                 \
        cp_commit();                                                              \
    } while (0)

    float acc[4][4][4];
#pragma unroll
    for (int mt = 0; mt < 4; mt++)
#pragma unroll
        for (int nt = 0; nt < 4; nt++)
#pragma unroll
            for (int q = 0; q < 4; q++) acc[mt][nt][q] = 0.f;

    PLOAD(0);
    PLOAD(1);

    for (int c = 0; c < C; c++) {
        cp_wait<1>();
        __syncthreads();
        if (c + 2 < C) PLOAD(c + 2);
        else cp_commit();

        int s = c % PSTAGE;
        uint32_t ahS = sAh + (uint32_t)(s * P_AB);
        uint32_t alS = sAl + (uint32_t)(s * P_AB);
        uint32_t bhS = sBh + (uint32_t)(s * P_BB);
        uint32_t blS = sBl + (uint32_t)(s * P_BB);

#pragma unroll
        for (int ks = 0; ks < 2; ks++) {
            uint32_t ah[4][4], al[4][4];
#pragma unroll
            for (int mt = 0; mt < 4; mt++) {
                ldsm4(ah[mt][0], ah[mt][1], ah[mt][2], ah[mt][3], ahS + offA[mt][ks]);
                ldsm4(al[mt][0], al[mt][1], al[mt][2], al[mt][3], alS + offA[mt][ks]);
            }
            uint32_t bh[2][4], bl[2][4];
#pragma unroll
            for (int p = 0; p < 2; p++) {
                ldsm4t(bh[p][0], bh[p][1], bh[p][2], bh[p][3], bhS + offB[ks][p]);
                ldsm4t(bl[p][0], bl[p][1], bl[p][2], bl[p][3], blS + offB[ks][p]);
            }
#pragma unroll
            for (int mt = 0; mt < 4; mt++)
#pragma unroll
                for (int nt = 0; nt < 4; nt++) {
                    int p = nt >> 1, q = (nt & 1) * 2;
                    mma_f16(acc[mt][nt][0], acc[mt][nt][1], acc[mt][nt][2], acc[mt][nt][3],
                            ah[mt][0], ah[mt][1], ah[mt][2], ah[mt][3],
                            bh[p][q], bh[p][q + 1]);
                    mma_f16(acc[mt][nt][0], acc[mt][nt][1], acc[mt][nt][2], acc[mt][nt][3],
                            ah[mt][0], ah[mt][1], ah[mt][2], ah[mt][3],
                            bl[p][q], bl[p][q + 1]);
                    mma_f16(acc[mt][nt][0], acc[mt][nt][1], acc[mt][nt][2], acc[mt][nt][3],
                            al[mt][0], al[mt][1], al[mt][2], al[mt][3],
                            bh[p][q], bh[p][q + 1]);
                }
        }
    }

#pragma unroll
    for (int mt = 0; mt < 4; mt++) {
        int r0 = m0 + wm * 64 + mt * 16 + g;
#pragma unroll
        for (int half = 0; half < 2; half++) {
            int r = r0 + half * 8;
            float* orow = g_t + (size_t)r * D_MODEL + n0;
#pragma unroll
            for (int nt = 0; nt < 4; nt++) {
                int col = wn * 32 + nt * 8 + 2 * tig;
                float v0 = acc[mt][nt][half * 2 + 0] + bias[n0 + col];
                float v1 = acc[mt][nt][half * 2 + 1] + bias[n0 + col + 1];
                float2 o = make_float2(gelu_exact(v0), gelu_exact(v1));
                *reinterpret_cast<float2*>(orow + col) = o;
            }
        }
    }
#undef PLOAD
}

// ---------------- router ----------------
__global__ void router_kernel(const float* __restrict__ swW, const float* __restrict__ swb)
{
    int tok = blockIdx.x, tid = threadIdx.x;
    const float* tr = g_t + (size_t)tok * D_MODEL;
    float a0 = 0.f, a1 = 0.f, a2 = 0.f, a3 = 0.f;
    for (int k = tid; k < D_MODEL; k += 256) {
        float tv = tr[k];
        const float* w = swW + (size_t)k * NEXP;
        a0 += tv * w[0]; a1 += tv * w[1]; a2 += tv * w[2]; a3 += tv * w[3];
    }
    __shared__ float red[4][256];
    red[0][tid] = a0; red[1][tid] = a1; red[2][tid] = a2; red[3][tid] = a3;
    __syncthreads();
    for (int o = 128; o > 0; o >>= 1) {
        if (tid < o) {
            red[0][tid] += red[0][tid + o]; red[1][tid] += red[1][tid + o];
            red[2][tid] += red[2][tid + o]; red[3][tid] += red[3][tid + o];
        }
        __syncthreads();
    }
    if (tid == 0) {
        float l[NEXP]; float mx = -1e30f; int arg = 0;
        for (int e = 0; e < NEXP; e++) {
            l[e] = red[e][0] + swb[e];
            if (l[e] > mx) { mx = l[e]; arg = e; }
        }
        float s = 0.f, p[NEXP];
        for (int e = 0; e < NEXP; e++) { p[e] = expf(l[e] - mx); s += p[e]; }
        float inv = 1.0f / s;
        for (int e = 0; e < NEXP; e++) g_probs[(size_t)tok * NEXP + e] = p[e] * inv;
        g_routes[tok] = arg;
        g_pmax[tok] = inv;
    }
}

__global__ void probsum_kernel()
{
    int e = blockIdx.x, tid = threadIdx.x;
    float s = 0.f;
    for (int t = tid; t < T_TOK; t += 256) s += g_probs[(size_t)t * NEXP + e];
    __shared__ float red[256];
    red[tid] = s; __syncthreads();
    for (int o = 128; o > 0; o >>= 1) { if (tid < o) red[tid] += red[tid + o]; __syncthreads(); }
    if (tid == 0) g_probsum[e] = red[0];
}

// ---------------- capacity scan ----------------
__global__ void scan_kernel()
{
    __shared__ int cnt[256][NEXP];
    int tid = threadIdx.x;
    const int CHUNK = T_TOK / 256;
    int base = tid * CHUNK;
    int c[NEXP] = {0, 0, 0, 0};
    for (int i = 0; i < CHUNK; i++) c[g_routes[base + i]]++;
    for (int e = 0; e < NEXP; e++) cnt[tid][e] = c[e];
    __syncthreads();
    if (tid == 0) {
        int run[NEXP] = {0, 0, 0, 0};
        for (int th = 0; th < 256; th++)
            for (int e = 0; e < NEXP; e++) {
                int tmp = cnt[th][e]; cnt[th][e] = run[e]; run[e] += tmp;
            }
        int nd = 0;
        for (int e = 0; e < NEXP; e++) {
            g_counts[e] = (float)run[e];
            int mf = run[e] < CAP ? run[e] : CAP;
            g_Mfill[e] = mf;
            nd += run[e] - mf;
        }
        g_ndrop[0] = (float)nd;
    }
    __syncthreads();
    int off[NEXP];
    for (int e = 0; e < NEXP; e++) off[e] = cnt[tid][e];
    for (int i = 0; i < CHUNK; i++) {
        int tok = base + i;
        int e = g_routes[tok];
        int p = off[e]++;
        int keep = (p < CAP) ? 1 : 0;
        g_keep[tok] = keep;
        if (keep) g_slot2tok[e * CAP + p] = tok;
    }
}

// ---------------- dispatch gather: g_ebh[slot] = fp16(g_t[tok]) ----------------
__global__ void dispatch_kernel()
{
    int slot = blockIdx.x;
    int e = slot / CAP, p = slot % CAP;
    if (p >= g_Mfill[e]) return;
    int tok = g_slot2tok[slot];
    uint2* dst = reinterpret_cast<uint2*>(g_ebh + (size_t)slot * D_MODEL);
    const float4* src = reinterpret_cast<const float4*>(g_t + (size_t)tok * D_MODEL);
    for (int i = threadIdx.x; i < D_MODEL / 4; i += 128) {
        float4 v = src[i];
        __half2 lo = __floats2half2_rn(v.x, v.y);
        __half2 hi = __floats2half2_rn(v.z, v.w);
        dst[i] = make_uint2(h2_u32(lo), h2_u32(hi));
    }
}

// ---------------- fp16 mma expert GEMMs: CTA tile 128x256, warp tile 64x64 ----------------
#define BM 128
#define BN 256
#define BK 32
#define A_BYTES (BM * 64)        // 8192
#define B_BYTES (BK * 512)       // 16384
#define NSTAGE 4
#define SMEM_MOE (NSTAGE * (A_BYTES + B_BYTES))   // 98304

template<int MODE>
__global__ void __launch_bounds__(256, 1)
moe_mma(const __half* __restrict__ Wh, const float* __restrict__ bias_all,
        float* __restrict__ out)
{
    const int K  = (MODE == 1) ? D_MODEL : H_FF;
    const int NT = (MODE == 1) ? H_FF : D_MODEL;
    const int C  = K / BK;

    int e = blockIdx.z;
    int mfill = g_Mfill[e];
    int m0 = blockIdx.x * BM;
    if (m0 >= mfill) return;
    int n0 = blockIdx.y * BN;

    extern __shared__ char smem[];
    uint32_t sA = smem_u32(smem);
    uint32_t sB = sA + NSTAGE * A_BYTES;

    int tid = threadIdx.x;
    int w = tid >> 5, lane = tid & 31;
    int wm = w >> 2, wn = w & 3;
    int g = lane >> 2, tig = lane & 3;
    int l15 = lane & 15, hi = lane >> 4;

    const __half* Abase = ((MODE == 1) ? g_ebh : g_hh) + (size_t)(e * CAP + m0) * K;
    const __half* Bbase = Wh + (size_t)e * K * NT;

    const __half* a_src[2]; uint32_t a_dst[2];
#pragma unroll
    for (int i = 0; i < 2; i++) {
        int idx = i * 256 + tid;
        int row = idx >> 2, kc = idx & 3;
        a_src[i] = Abase + (size_t)row * K + kc * 8;
        a_dst[i] = (uint32_t)(row * 64 + ((kc ^ ((row >> 1) & 3)) * 16));
    }
    const __half* b_src[4]; uint32_t b_dst[4];
#pragma unroll
    for (int i = 0; i < 4; i++) {
        int idx = i * 256 + tid;
        int row = idx >> 5, nc = idx & 31;
        b_src[i] = Bbase + (size_t)row * NT + n0 + nc * 8;
        b_dst[i] = (uint32_t)(row * 512 + ((nc ^ (row & 7)) * 16));
    }

    uint32_t offA[4][2];
#pragma unroll
    for (int mt = 0; mt < 4; mt++) {
        int row = wm * 64 + mt * 16 + l15;
        int xr = (row >> 1) & 3;
#pragma unroll
        for (int ks = 0; ks < 2; ks++)
            offA[mt][ks] = (uint32_t)(row * 64 + (((ks * 2 + hi) ^ xr) * 16));
    }
    uint32_t offB[2][4];
#pragma unroll
    for (int ks = 0; ks < 2; ks++) {
        int row = ks * 16 + l15;
#pragma unroll
        for (int p = 0; p < 4; p++) {
            int chunk = wn * 8 + p * 2 + hi;
            offB[ks][p] = (uint32_t)(row * 512 + ((chunk ^ (row & 7)) * 16));
        }
    }

#define LOAD_STAGE(c) do {                                                        \
        int s_ = (c) & (NSTAGE - 1);                                              \
        uint32_t aS = sA + (uint32_t)(s_ * A_BYTES);                              \
        uint32_t bS = sB + (uint32_t)(s_ * B_BYTES);                              \
        cp16(aS + a_dst[0], a_src[0] + (c) * BK);                                 \
        cp16(aS + a_dst[1], a_src[1] + (c) * BK);                                 \
        cp16(bS + b_dst[0], b_src[0] + (size_t)(c) * BK * NT);                    \
        cp16(bS + b_dst[1], b_src[1] + (size_t)(c) * BK * NT);                    \
        cp16(bS + b_dst[2], b_src[2] + (size_t)(c) * BK * NT);                    \
        cp16(bS + b_dst[3], b_src[3] + (size_t)(c) * BK * NT);                    \
        cp_commit();                                                              \
    } while (0)

    float acc[4][8][4];
#pragma unroll
    for (int mt = 0; mt < 4; mt++)
#pragma unroll
        for (int nt = 0; nt < 8; nt++)
#pragma unroll
            for (int q = 0; q < 4; q++) acc[mt][nt][q] = 0.f;

    LOAD_STAGE(0);
    LOAD_STAGE(1);
    LOAD_STAGE(2);

    for (int c = 0; c < C; c++) {
        cp_wait<2>();
        __syncthreads();
        if (c + 3 < C) LOAD_STAGE(c + 3);
        else cp_commit();

        int s = c & (NSTAGE - 1);
        uint32_t aS = sA + (uint32_t)(s * A_BYTES);
        uint32_t bS = sB + (uint32_t)(s * B_BYTES);

#pragma unroll
        for (int ks = 0; ks < 2; ks++) {
            uint32_t a[4][4];
#pragma unroll
            for (int mt = 0; mt < 4; mt++)
                ldsm4(a[mt][0], a[mt][1], a[mt][2], a[mt][3], aS + offA[mt][ks]);
            uint32_t b[4][4];
#pragma unroll
            for (int p = 0; p < 4; p++)
                ldsm4t(b[p][0], b[p][1], b[p][2], b[p][3], bS + offB[ks][p]);
#pragma unroll
            for (int mt = 0; mt < 4; mt++)
#pragma unroll
                for (int nt = 0; nt < 8; nt++) {
                    int p = nt >> 1, q = (nt & 1) * 2;
                    mma_f16(acc[mt][nt][0], acc[mt][nt][1], acc[mt][nt][2], acc[mt][nt][3],
                            a[mt][0], a[mt][1], a[mt][2], a[mt][3],
                            b[p][q], b[p][q + 1]);
                }
        }
    }

    const float* bias = bias_all + (size_t)e * NT + n0;
#pragma unroll
    for (int mt = 0; mt < 4; mt++) {
        int r0 = m0 + wm * 64 + mt * 16 + g;
#pragma unroll
        for (int half = 0; half < 2; half++) {
            int r = r0 + half * 8;
            if (r >= mfill) continue;
#pragma unroll
            for (int nt = 0; nt < 8; nt++) {
                int col = wn * 64 + nt * 8 + 2 * tig;
                float v0 = acc[mt][nt][half * 2 + 0] + bias[col];
                float v1 = acc[mt][nt][half * 2 + 1] + bias[col + 1];
                if (MODE == 1) {
                    __half2 h2 = __floats2half2_rn(gelu_exact(v0), gelu_exact(v1));
                    *reinterpret_cast<uint32_t*>(
                        g_hh + (size_t)(e * CAP + r) * H_FF + n0 + col) = h2_u32(h2);
                } else {
                    int tok = g_slot2tok[e * CAP + r];
                    float pm = g_pmax[tok];
                    float2 o = make_float2(v0 * pm, v1 * pm);
                    *reinterpret_cast<float2*>(out + (size_t)tok * D_MODEL + n0 + col) = o;
                }
            }
        }
    }
#undef LOAD_STAGE
}

// ---------------- dropped tokens ----------------
__global__ void dropped_kernel(float* __restrict__ out)
{
    int tok = blockIdx.x;
    if (g_keep[tok]) return;
    float pm = g_pmax[tok];
    const float* tr = g_t + (size_t)tok * D_MODEL;
    float* orow = out + (size_t)tok * D_MODEL;
    for (int c = threadIdx.x; c < D_MODEL; c += 256) orow[c] = tr[c] * pm;
}

// ---------------- extras ----------------
__global__ void extras_kernel(float* __restrict__ out, int out_size)
{
    int i = blockIdx.x * 256 + threadIdx.x;
    if (i >= OUT_EXTRAS_N) return;
    long long off = (long long)OUT_COUNTS + i;
    if (off >= (long long)out_size) return;
    float v;
    if (i < 4)       v = g_counts[i];
    else if (i < 8)  v = g_probsum[i - 4];
    else if (i == 8) v = g_ndrop[0];
    else             v = g_pmax[i - 9];
    out[off] = v;
}

// ---------------- launch ----------------
extern "C" void kernel_launch(void* const* d_in, const int* in_sizes, int n_in,
                              void* d_out, int out_size)
{
    const float* x     = (const float*)d_in[0];
    const float* ln_g  = (const float*)d_in[1];
    const float* ln_b  = (const float*)d_in[2];
    const float* pre_W = (const float*)d_in[3];
    const float* pre_b = (const float*)d_in[4];
    const float* sw_W  = (const float*)d_in[5];
    const float* sw_b  = (const float*)d_in[6];
    const float* W1    = (const float*)d_in[7];
    const float* b1    = (const float*)d_in[8];
    const float* W2    = (const float*)d_in[9];
    const float* b2    = (const float*)d_in[10];
    float* out = (float*)d_out;

    __half *d_W1h, *d_W2h, *d_Wph, *d_Wpl;
    cudaGetSymbolAddress((void**)&d_W1h, g_W1h);
    cudaGetSymbolAddress((void**)&d_W2h, g_W2h);
    cudaGetSymbolAddress((void**)&d_Wph, g_Wph);
    cudaGetSymbolAddress((void**)&d_Wpl, g_Wpl);
    cudaFuncSetAttribute(moe_mma<1>, cudaFuncAttributeMaxDynamicSharedMemorySize, SMEM_MOE);
    cudaFuncSetAttribute(moe_mma<2>, cudaFuncAttributeMaxDynamicSharedMemorySize, SMEM_MOE);
    cudaFuncSetAttribute(pre_mma, cudaFuncAttributeMaxDynamicSharedMemorySize, SMEM_PRE);

    // one-time handles (host-side only; no device memory, work graph unchanged)
    static cudaStream_t s1 = nullptr;
    static cudaEvent_t eFork, eSplit, eW1, eW2;
    if (!s1) {
        cudaStreamCreateWithFlags(&s1, cudaStreamNonBlocking);
        cudaEventCreateWithFlags(&eFork,  cudaEventDisableTiming);
        cudaEventCreateWithFlags(&eSplit, cudaEventDisableTiming);
        cudaEventCreateWithFlags(&eW1,    cudaEventDisableTiming);
        cudaEventCreateWithFlags(&eW2,    cudaEventDisableTiming);
    }

    const size_t WN4 = (size_t)NEXP * D_MODEL * H_FF / 4;

    // fork: weight prep on s1, hidden under the ln -> pre -> router chain
    cudaEventRecord(eFork, 0);
    cudaStreamWaitEvent(s1, eFork, 0);
    split_w<<<256, 256, 0, s1>>>(pre_W, d_Wph, d_Wpl, (size_t)D_IN * D_MODEL);
    cudaEventRecord(eSplit, s1);
    convert_w<<<2048, 256, 0, s1>>>(W1, d_W1h, WN4);
    cudaEventRecord(eW1, s1);
    convert_w<<<2048, 256, 0, s1>>>(W2, d_W2h, WN4);
    cudaEventRecord(eW2, s1);

    // main chain
    ln_kernel<<<T_TOK, 256>>>(x, ln_g, ln_b);
    cudaStreamWaitEvent(0, eSplit, 0);
    pre_mma<<<dim3(T_TOK / PBM, D_MODEL / PBN), 256, SMEM_PRE>>>(pre_b);
    router_kernel<<<T_TOK, 256>>>(sw_W, sw_b);
    probsum_kernel<<<NEXP, 256>>>();
    scan_kernel<<<1, 256>>>();
    dispatch_kernel<<<ECAP, 128>>>();
    cudaStreamWaitEvent(0, eW1, 0);
    moe_mma<1><<<dim3(CAP / BM, H_FF / BN, NEXP), 256, SMEM_MOE>>>(d_W1h, b1, nullptr);
    cudaStreamWaitEvent(0, eW2, 0);
    moe_mma<2><<<dim3(CAP / BM, D_MODEL / BN, NEXP), 256, SMEM_MOE>>>(d_W2h, b2, out);
    dropped_kernel<<<T_TOK, 256>>>(out);
    extras_kernel<<<(OUT_EXTRAS_N + 255) / 256, 256>>>(out, out_size);
}

// round 17
// speedup vs baseline: 1.2412x; 1.0870x over previous
#include <cuda_runtime.h>
#include <cuda_fp16.h>
#include <math.h>
#include <stdint.h>

// ---------------- problem dims (fixed) ----------------
#define BATCH   16
#define SEQ     576
#define T_TOK   9216
#define D_IN    1024
#define D_MODEL 2048
#define NEXP    4
#define H_FF    8192
#define CAP     3456
#define ECAP    (NEXP*CAP)      // 13824

#define OUT_COUNTS  (T_TOK*D_MODEL)
#define OUT_EXTRAS_N 9225

// ---------------- scratch ----------------
__device__ float  g_t [(size_t)T_TOK * D_MODEL];
__device__ float  g_probs[(size_t)T_TOK * NEXP];
__device__ float  g_pmax [T_TOK];
__device__ int    g_routes[T_TOK];
__device__ int    g_keep  [T_TOK];
__device__ int    g_slot2tok[ECAP];
__device__ int    g_Mfill[NEXP];
__device__ float  g_counts[NEXP];
__device__ float  g_probsum[NEXP];
__device__ float  g_ndrop[1];
__device__ __half g_xh[(size_t)T_TOK * D_IN];
__device__ __half g_xl[(size_t)T_TOK * D_IN];
__device__ __half g_Wph[(size_t)D_IN * D_MODEL];
__device__ __half g_Wpl[(size_t)D_IN * D_MODEL];
__device__ __half g_ebh[(size_t)ECAP * D_MODEL];
__device__ __half g_hh [(size_t)ECAP * H_FF];
__device__ __half g_W1h[(size_t)NEXP * D_MODEL * H_FF];
__device__ __half g_W2h[(size_t)NEXP * H_FF * D_MODEL];

__device__ __forceinline__ float gelu_exact(float x) {
    return 0.5f * x * (1.0f + erff(x * 0.70710678118654752f));
}
__device__ __forceinline__ uint32_t h2_u32(__half2 h) {
    return *reinterpret_cast<uint32_t*>(&h);
}
__device__ __forceinline__ uint32_t smem_u32(const void* p) {
    uint32_t a;
    asm("{ .reg .u64 t; cvta.to.shared.u64 t, %1; cvt.u32.u64 %0, t; }" : "=r"(a) : "l"(p));
    return a;
}
__device__ __forceinline__ void cp16(uint32_t dst, const void* src) {
    asm volatile("cp.async.cg.shared.global [%0], [%1], 16;" :: "r"(dst), "l"(src) : "memory");
}
__device__ __forceinline__ void cp_commit() { asm volatile("cp.async.commit_group;" ::: "memory"); }
template<int N> __device__ __forceinline__ void cp_wait() {
    asm volatile("cp.async.wait_group %0;" :: "n"(N) : "memory");
}
__device__ __forceinline__ void ldsm4(uint32_t& r0, uint32_t& r1, uint32_t& r2, uint32_t& r3,
                                      uint32_t addr) {
    asm volatile("ldmatrix.sync.aligned.m8n8.x4.shared.b16 {%0,%1,%2,%3}, [%4];"
                 : "=r"(r0), "=r"(r1), "=r"(r2), "=r"(r3) : "r"(addr));
}
__device__ __forceinline__ void ldsm4t(uint32_t& r0, uint32_t& r1, uint32_t& r2, uint32_t& r3,
                                       uint32_t addr) {
    asm volatile("ldmatrix.sync.aligned.m8n8.x4.trans.shared.b16 {%0,%1,%2,%3}, [%4];"
                 : "=r"(r0), "=r"(r1), "=r"(r2), "=r"(r3) : "r"(addr));
}
__device__ __forceinline__ void mma_f16(float& c0, float& c1, float& c2, float& c3,
                                        uint32_t a0, uint32_t a1, uint32_t a2, uint32_t a3,
                                        uint32_t b0, uint32_t b1) {
    asm volatile(
        "mma.sync.aligned.m16n8k16.row.col.f32.f16.f16.f32 "
        "{%0,%1,%2,%3}, {%4,%5,%6,%7}, {%8,%9}, {%0,%1,%2,%3};"
        : "+f"(c0), "+f"(c1), "+f"(c2), "+f"(c3)
        : "r"(a0), "r"(a1), "r"(a2), "r"(a3), "r"(b0), "r"(b1));
}

// ---------------- LayerNorm -> split fp16 hi/lo ----------------
__global__ void ln_kernel(const float* __restrict__ x,
                          const float* __restrict__ g,
                          const float* __restrict__ b)
{
    int tok = blockIdx.x, tid = threadIdx.x;
    const float* xr = x + (size_t)tok * D_IN;
    __shared__ float red[256];
    float s = 0.f;
    for (int i = tid; i < D_IN; i += 256) s += xr[i];
    red[tid] = s; __syncthreads();
    for (int o = 128; o > 0; o >>= 1) { if (tid < o) red[tid] += red[tid + o]; __syncthreads(); }
    float mu = red[0] * (1.0f / D_IN);
    __syncthreads();
    float v = 0.f;
    for (int i = tid; i < D_IN; i += 256) { float d = xr[i] - mu; v += d * d; }
    red[tid] = v; __syncthreads();
    for (int o = 128; o > 0; o >>= 1) { if (tid < o) red[tid] += red[tid + o]; __syncthreads(); }
    float rstd = rsqrtf(red[0] * (1.0f / D_IN) + 1e-5f);
    __half* oh = g_xh + (size_t)tok * D_IN;
    __half* ol = g_xl + (size_t)tok * D_IN;
    for (int i = tid; i < D_IN; i += 256) {
        float xv = (xr[i] - mu) * rstd * g[i] + b[i];
        __half h = __float2half_rn(xv);
        oh[i] = h;
        ol[i] = __float2half_rn(xv - __half2float(h));
    }
}

// ---------------- weight split fp32 -> fp16 hi/lo ----------------
__global__ void split_w(const float* __restrict__ in, __half* __restrict__ oh,
                        __half* __restrict__ ol, size_t n)
{
    size_t i = (size_t)blockIdx.x * blockDim.x + threadIdx.x;
    size_t stride = (size_t)gridDim.x * blockDim.x;
    for (; i < n; i += stride) {
        float v = in[i];
        __half h = __float2half_rn(v);
        oh[i] = h;
        ol[i] = __float2half_rn(v - __half2float(h));
    }
}

// ---------------- weight convert fp32 -> fp16 ----------------
__global__ void convert_w(const float* __restrict__ in, __half* __restrict__ out, size_t n4)
{
    size_t i = (size_t)blockIdx.x * blockDim.x + threadIdx.x;
    size_t stride = (size_t)gridDim.x * blockDim.x;
    const float4* I = reinterpret_cast<const float4*>(in);
    uint2* O = reinterpret_cast<uint2*>(out);
    for (; i < n4; i += stride) {
        float4 v = I[i];
        __half2 lo = __floats2half2_rn(v.x, v.y);
        __half2 hi = __floats2half2_rn(v.z, v.w);
        O[i] = make_uint2(h2_u32(lo), h2_u32(hi));
    }
}

// ---------------- split-fp16 pre-GEMM ----------------
#define PBM 128
#define PBN 128
#define PBK 32
#define P_AB (PBM * 64)
#define P_BB (PBK * 256)
#define PSTAGE 3
#define SMEM_PRE (PSTAGE * 2 * (P_AB + P_BB))   // 98304

__global__ void __launch_bounds__(256, 1)
pre_mma(const float* __restrict__ bias)
{
    const int K = D_IN, NT = D_MODEL, C = K / PBK;

    int m0 = blockIdx.x * PBM;
    int n0 = blockIdx.y * PBN;

    extern __shared__ char smem[];
    uint32_t sAh = smem_u32(smem);
    uint32_t sAl = sAh + PSTAGE * P_AB;
    uint32_t sBh = sAl + PSTAGE * P_AB;
    uint32_t sBl = sBh + PSTAGE * P_BB;

    int tid = threadIdx.x;
    int w = tid >> 5, lane = tid & 31;
    int wm = w >> 2, wn = w & 3;
    int g = lane >> 2, tig = lane & 3;
    int l15 = lane & 15, hi = lane >> 4;

    const __half* Ah = g_xh + (size_t)m0 * K;
    const __half* Al = g_xl + (size_t)m0 * K;

    const __half* ah_src[2]; const __half* al_src[2]; uint32_t a_dst[2];
#pragma unroll
    for (int i = 0; i < 2; i++) {
        int idx = i * 256 + tid;
        int row = idx >> 2, kc = idx & 3;
        ah_src[i] = Ah + (size_t)row * K + kc * 8;
        al_src[i] = Al + (size_t)row * K + kc * 8;
        a_dst[i] = (uint32_t)(row * 64 + ((kc ^ ((row >> 1) & 3)) * 16));
    }
    const __half* bh_src[2]; const __half* bl_src[2]; uint32_t b_dst[2];
#pragma unroll
    for (int i = 0; i < 2; i++) {
        int idx = i * 256 + tid;
        int row = idx >> 4, nc = idx & 15;
        bh_src[i] = g_Wph + (size_t)row * NT + n0 + nc * 8;
        bl_src[i] = g_Wpl + (size_t)row * NT + n0 + nc * 8;
        b_dst[i] = (uint32_t)(row * 256 + ((nc ^ (row & 7)) * 16));
    }

    uint32_t offA[4][2];
#pragma unroll
    for (int mt = 0; mt < 4; mt++) {
        int row = wm * 64 + mt * 16 + l15;
        int xr = (row >> 1) & 3;
#pragma unroll
        for (int ks = 0; ks < 2; ks++)
            offA[mt][ks] = (uint32_t)(row * 64 + (((ks * 2 + hi) ^ xr) * 16));
    }
    uint32_t offB[2][2];
#pragma unroll
    for (int ks = 0; ks < 2; ks++) {
        int row = ks * 16 + l15;
#pragma unroll
        for (int p = 0; p < 2; p++) {
            int chunk = wn * 4 + p * 2 + hi;
            offB[ks][p] = (uint32_t)(row * 256 + ((chunk ^ (row & 7)) * 16));
        }
    }

#define PLOAD(c) do {                                                             \
        int s_ = (c) % PSTAGE;                                                    \
        uint32_t ahS = sAh + (uint32_t)(s_ * P_AB);                               \
        uint32_t alS = sAl + (uint32_t)(s_ * P_AB);                               \
        uint32_t bhS = sBh + (uint32_t)(s_ * P_BB);                               \
        uint32_t blS = sBl + (uint32_t)(s_ * P_BB);                               \
        cp16(ahS + a_dst[0], ah_src[0] + (c) * PBK);                              \
        cp16(ahS + a_dst[1], ah_src[1] + (c) * PBK);                              \
        cp16(alS + a_dst[0], al_src[0] + (c) * PBK);                              \
        cp16(alS + a_dst[1], al_src[1] + (c) * PBK);                              \
        cp16(bhS + b_dst[0], bh_src[0] + (size_t)(c) * PBK * NT);                 \
        cp16(bhS + b_dst[1], bh_src[1] + (size_t)(c) * PBK * NT);                 \
        cp16(blS + b_dst[0], bl_src[0] + (size_t)(c) * PBK * NT);                 \
        cp16(blS + b_dst[1], bl_src[1] + (size_t)(c) * PBK * NT);                 \
        cp_commit();                                                              \
    } while (0)

    float acc[4][4][4];
#pragma unroll
    for (int mt = 0; mt < 4; mt++)
#pragma unroll
        for (int nt = 0; nt < 4; nt++)
#pragma unroll
            for (int q = 0; q < 4; q++) acc[mt][nt][q] = 0.f;

    PLOAD(0);
    PLOAD(1);

    for (int c = 0; c < C; c++) {
        cp_wait<1>();
        __syncthreads();
        if (c + 2 < C) PLOAD(c + 2);
        else cp_commit();

        int s = c % PSTAGE;
        uint32_t ahS = sAh + (uint32_t)(s * P_AB);
        uint32_t alS = sAl + (uint32_t)(s * P_AB);
        uint32_t bhS = sBh + (uint32_t)(s * P_BB);
        uint32_t blS = sBl + (uint32_t)(s * P_BB);

#pragma unroll
        for (int ks = 0; ks < 2; ks++) {
            uint32_t ah[4][4], al[4][4];
#pragma unroll
            for (int mt = 0; mt < 4; mt++) {
                ldsm4(ah[mt][0], ah[mt][1], ah[mt][2], ah[mt][3], ahS + offA[mt][ks]);
                ldsm4(al[mt][0], al[mt][1], al[mt][2], al[mt][3], alS + offA[mt][ks]);
            }
            uint32_t bh[2][4], bl[2][4];
#pragma unroll
            for (int p = 0; p < 2; p++) {
                ldsm4t(bh[p][0], bh[p][1], bh[p][2], bh[p][3], bhS + offB[ks][p]);
                ldsm4t(bl[p][0], bl[p][1], bl[p][2], bl[p][3], blS + offB[ks][p]);
            }
#pragma unroll
            for (int mt = 0; mt < 4; mt++)
#pragma unroll
                for (int nt = 0; nt < 4; nt++) {
                    int p = nt >> 1, q = (nt & 1) * 2;
                    mma_f16(acc[mt][nt][0], acc[mt][nt][1], acc[mt][nt][2], acc[mt][nt][3],
                            ah[mt][0], ah[mt][1], ah[mt][2], ah[mt][3],
                            bh[p][q], bh[p][q + 1]);
                    mma_f16(acc[mt][nt][0], acc[mt][nt][1], acc[mt][nt][2], acc[mt][nt][3],
                            ah[mt][0], ah[mt][1], ah[mt][2], ah[mt][3],
                            bl[p][q], bl[p][q + 1]);
                    mma_f16(acc[mt][nt][0], acc[mt][nt][1], acc[mt][nt][2], acc[mt][nt][3],
                            al[mt][0], al[mt][1], al[mt][2], al[mt][3],
                            bh[p][q], bh[p][q + 1]);
                }
        }
    }

#pragma unroll
    for (int mt = 0; mt < 4; mt++) {
        int r0 = m0 + wm * 64 + mt * 16 + g;
#pragma unroll
        for (int half = 0; half < 2; half++) {
            int r = r0 + half * 8;
            float* orow = g_t + (size_t)r * D_MODEL + n0;
#pragma unroll
            for (int nt = 0; nt < 4; nt++) {
                int col = wn * 32 + nt * 8 + 2 * tig;
                float v0 = acc[mt][nt][half * 2 + 0] + bias[n0 + col];
                float v1 = acc[mt][nt][half * 2 + 1] + bias[n0 + col + 1];
                float2 o = make_float2(gelu_exact(v0), gelu_exact(v1));
                *reinterpret_cast<float2*>(orow + col) = o;
            }
        }
    }
#undef PLOAD
}

// ---------------- router ----------------
__global__ void router_kernel(const float* __restrict__ swW, const float* __restrict__ swb)
{
    int tok = blockIdx.x, tid = threadIdx.x;
    const float* tr = g_t + (size_t)tok * D_MODEL;
    float a0 = 0.f, a1 = 0.f, a2 = 0.f, a3 = 0.f;
    for (int k = tid; k < D_MODEL; k += 256) {
        float tv = tr[k];
        const float* w = swW + (size_t)k * NEXP;
        a0 += tv * w[0]; a1 += tv * w[1]; a2 += tv * w[2]; a3 += tv * w[3];
    }
    __shared__ float red[4][256];
    red[0][tid] = a0; red[1][tid] = a1; red[2][tid] = a2; red[3][tid] = a3;
    __syncthreads();
    for (int o = 128; o > 0; o >>= 1) {
        if (tid < o) {
            red[0][tid] += red[0][tid + o]; red[1][tid] += red[1][tid + o];
            red[2][tid] += red[2][tid + o]; red[3][tid] += red[3][tid + o];
        }
        __syncthreads();
    }
    if (tid == 0) {
        float l[NEXP]; float mx = -1e30f; int arg = 0;
        for (int e = 0; e < NEXP; e++) {
            l[e] = red[e][0] + swb[e];
            if (l[e] > mx) { mx = l[e]; arg = e; }
        }
        float s = 0.f, p[NEXP];
        for (int e = 0; e < NEXP; e++) { p[e] = expf(l[e] - mx); s += p[e]; }
        float inv = 1.0f / s;
        for (int e = 0; e < NEXP; e++) g_probs[(size_t)tok * NEXP + e] = p[e] * inv;
        g_routes[tok] = arg;
        g_pmax[tok] = inv;
    }
}

__global__ void probsum_kernel()
{
    int e = blockIdx.x, tid = threadIdx.x;
    float s = 0.f;
    for (int t = tid; t < T_TOK; t += 256) s += g_probs[(size_t)t * NEXP + e];
    __shared__ float red[256];
    red[tid] = s; __syncthreads();
    for (int o = 128; o > 0; o >>= 1) { if (tid < o) red[tid] += red[tid + o]; __syncthreads(); }
    if (tid == 0) g_probsum[e] = red[0];
}

// ---------------- capacity scan ----------------
__global__ void scan_kernel()
{
    __shared__ int cnt[256][NEXP];
    int tid = threadIdx.x;
    const int CHUNK = T_TOK / 256;
    int base = tid * CHUNK;
    int c[NEXP] = {0, 0, 0, 0};
    for (int i = 0; i < CHUNK; i++) c[g_routes[base + i]]++;
    for (int e = 0; e < NEXP; e++) cnt[tid][e] = c[e];
    __syncthreads();
    if (tid == 0) {
        int run[NEXP] = {0, 0, 0, 0};
        for (int th = 0; th < 256; th++)
            for (int e = 0; e < NEXP; e++) {
                int tmp = cnt[th][e]; cnt[th][e] = run[e]; run[e] += tmp;
            }
        int nd = 0;
        for (int e = 0; e < NEXP; e++) {
            g_counts[e] = (float)run[e];
            int mf = run[e] < CAP ? run[e] : CAP;
            g_Mfill[e] = mf;
            nd += run[e] - mf;
        }
        g_ndrop[0] = (float)nd;
    }
    __syncthreads();
    int off[NEXP];
    for (int e = 0; e < NEXP; e++) off[e] = cnt[tid][e];
    for (int i = 0; i < CHUNK; i++) {
        int tok = base + i;
        int e = g_routes[tok];
        int p = off[e]++;
        int keep = (p < CAP) ? 1 : 0;
        g_keep[tok] = keep;
        if (keep) g_slot2tok[e * CAP + p] = tok;
    }
}

// ---------------- dispatch gather: g_ebh[slot] = fp16(g_t[tok]) ----------------
__global__ void dispatch_kernel()
{
    int slot = blockIdx.x;
    int e = slot / CAP, p = slot % CAP;
    if (p >= g_Mfill[e]) return;
    int tok = g_slot2tok[slot];
    uint2* dst = reinterpret_cast<uint2*>(g_ebh + (size_t)slot * D_MODEL);
    const float4* src = reinterpret_cast<const float4*>(g_t + (size_t)tok * D_MODEL);
    for (int i = threadIdx.x; i < D_MODEL / 4; i += 128) {
        float4 v = src[i];
        __half2 lo = __floats2half2_rn(v.x, v.y);
        __half2 hi = __floats2half2_rn(v.z, v.w);
        dst[i] = make_uint2(h2_u32(lo), h2_u32(hi));
    }
}

// ---------------- fp16 mma expert GEMMs: CTA 128x256x64, warp tile 64x64 ----------------
#define BM 128
#define BN 256
#define BK 64
#define A_BYTES (BM * 128)       // 16384 (128B rows, 8 chunks)
#define B_BYTES (BK * 512)       // 32768
#define NSTAGE 3
#define SMEM_MOE (NSTAGE * (A_BYTES + B_BYTES))   // 147456

template<int MODE>
__global__ void __launch_bounds__(256, 1)
moe_mma(const __half* __restrict__ Wh, const float* __restrict__ bias_all,
        float* __restrict__ out)
{
    const int K  = (MODE == 1) ? D_MODEL : H_FF;
    const int NT = (MODE == 1) ? H_FF : D_MODEL;
    const int C  = K / BK;

    int e = blockIdx.z;
    int mfill = g_Mfill[e];
    int m0 = blockIdx.x * BM;
    if (m0 >= mfill) return;
    int n0 = blockIdx.y * BN;

    extern __shared__ char smem[];
    uint32_t sA = smem_u32(smem);
    uint32_t sB = sA + NSTAGE * A_BYTES;

    int tid = threadIdx.x;
    int w = tid >> 5, lane = tid & 31;
    int wm = w >> 2, wn = w & 3;
    int g = lane >> 2, tig = lane & 3;
    int l15 = lane & 15, hi = lane >> 4;

    const __half* Abase = ((MODE == 1) ? g_ebh : g_hh) + (size_t)(e * CAP + m0) * K;
    const __half* Bbase = Wh + (size_t)e * K * NT;

    // cp.async: A 4 slots/thread (1024 chunks), B 8 slots/thread (2048 chunks)
    const __half* a_src[4]; uint32_t a_dst[4];
#pragma unroll
    for (int i = 0; i < 4; i++) {
        int idx = i * 256 + tid;
        int row = idx >> 3, kc = idx & 7;        // 8 chunks per 128B row
        a_src[i] = Abase + (size_t)row * K + kc * 8;
        a_dst[i] = (uint32_t)(row * 128 + ((kc ^ (row & 7)) * 16));
    }
    const __half* b_src[8]; uint32_t b_dst[8];
#pragma unroll
    for (int i = 0; i < 8; i++) {
        int idx = i * 256 + tid;
        int row = idx >> 5, nc = idx & 31;       // 32 chunks per 512B row
        b_src[i] = Bbase + (size_t)row * NT + n0 + nc * 8;
        b_dst[i] = (uint32_t)(row * 512 + ((nc ^ (row & 7)) * 16));
    }

    uint32_t offA[4][4];
#pragma unroll
    for (int mt = 0; mt < 4; mt++) {
        int row = wm * 64 + mt * 16 + l15;
        int xr = row & 7;
#pragma unroll
        for (int ks = 0; ks < 4; ks++)
            offA[mt][ks] = (uint32_t)(row * 128 + (((ks * 2 + hi) ^ xr) * 16));
    }
    uint32_t offB[4][4];
#pragma unroll
    for (int ks = 0; ks < 4; ks++) {
        int row = ks * 16 + l15;
#pragma unroll
        for (int p = 0; p < 4; p++) {
            int chunk = wn * 8 + p * 2 + hi;
            offB[ks][p] = (uint32_t)(row * 512 + ((chunk ^ (row & 7)) * 16));
        }
    }

#define LOAD_STAGE(c) do {                                                        \
        int s_ = (c) % NSTAGE;                                                    \
        uint32_t aS = sA + (uint32_t)(s_ * A_BYTES);                              \
        uint32_t bS = sB + (uint32_t)(s_ * B_BYTES);                              \
        _Pragma("unroll")                                                         \
        for (int i = 0; i < 4; i++) cp16(aS + a_dst[i], a_src[i] + (c) * BK);     \
        _Pragma("unroll")                                                         \
        for (int i = 0; i < 8; i++) cp16(bS + b_dst[i], b_src[i] + (size_t)(c) * BK * NT); \
        cp_commit();                                                              \
    } while (0)

    float acc[4][8][4];
#pragma unroll
    for (int mt = 0; mt < 4; mt++)
#pragma unroll
        for (int nt = 0; nt < 8; nt++)
#pragma unroll
            for (int q = 0; q < 4; q++) acc[mt][nt][q] = 0.f;

    LOAD_STAGE(0);
    LOAD_STAGE(1);

    for (int c = 0; c < C; c++) {
        cp_wait<1>();
        __syncthreads();
        if (c + 2 < C) LOAD_STAGE(c + 2);
        else cp_commit();

        int s = c % NSTAGE;
        uint32_t aS = sA + (uint32_t)(s * A_BYTES);
        uint32_t bS = sB + (uint32_t)(s * B_BYTES);

#pragma unroll
        for (int ks = 0; ks < 4; ks++) {
            uint32_t a[4][4];
#pragma unroll
            for (int mt = 0; mt < 4; mt++)
                ldsm4(a[mt][0], a[mt][1], a[mt][2], a[mt][3], aS + offA[mt][ks]);
            uint32_t b[4][4];
#pragma unroll
            for (int p = 0; p < 4; p++)
                ldsm4t(b[p][0], b[p][1], b[p][2], b[p][3], bS + offB[ks][p]);
#pragma unroll
            for (int mt = 0; mt < 4; mt++)
#pragma unroll
                for (int nt = 0; nt < 8; nt++) {
                    int p = nt >> 1, q = (nt & 1) * 2;
                    mma_f16(acc[mt][nt][0], acc[mt][nt][1], acc[mt][nt][2], acc[mt][nt][3],
                            a[mt][0], a[mt][1], a[mt][2], a[mt][3],
                            b[p][q], b[p][q + 1]);
                }
        }
    }

    const float* bias = bias_all + (size_t)e * NT + n0;
#pragma unroll
    for (int mt = 0; mt < 4; mt++) {
        int r0 = m0 + wm * 64 + mt * 16 + g;
#pragma unroll
        for (int half = 0; half < 2; half++) {
            int r = r0 + half * 8;
            if (r >= mfill) continue;
#pragma unroll
            for (int nt = 0; nt < 8; nt++) {
                int col = wn * 64 + nt * 8 + 2 * tig;
                float v0 = acc[mt][nt][half * 2 + 0] + bias[col];
                float v1 = acc[mt][nt][half * 2 + 1] + bias[col + 1];
                if (MODE == 1) {
                    __half2 h2 = __floats2half2_rn(gelu_exact(v0), gelu_exact(v1));
                    *reinterpret_cast<uint32_t*>(
                        g_hh + (size_t)(e * CAP + r) * H_FF + n0 + col) = h2_u32(h2);
                } else {
                    int tok = g_slot2tok[e * CAP + r];
                    float pm = g_pmax[tok];
                    float2 o = make_float2(v0 * pm, v1 * pm);
                    *reinterpret_cast<float2*>(out + (size_t)tok * D_MODEL + n0 + col) = o;
                }
            }
        }
    }
#undef LOAD_STAGE
}

// ---------------- dropped tokens ----------------
__global__ void dropped_kernel(float* __restrict__ out)
{
    int tok = blockIdx.x;
    if (g_keep[tok]) return;
    float pm = g_pmax[tok];
    const float* tr = g_t + (size_t)tok * D_MODEL;
    float* orow = out + (size_t)tok * D_MODEL;
    for (int c = threadIdx.x; c < D_MODEL; c += 256) orow[c] = tr[c] * pm;
}

// ---------------- extras ----------------
__global__ void extras_kernel(float* __restrict__ out, int out_size)
{
    int i = blockIdx.x * 256 + threadIdx.x;
    if (i >= OUT_EXTRAS_N) return;
    long long off = (long long)OUT_COUNTS + i;
    if (off >= (long long)out_size) return;
    float v;
    if (i < 4)       v = g_counts[i];
    else if (i < 8)  v = g_probsum[i - 4];
    else if (i == 8) v = g_ndrop[0];
    else             v = g_pmax[i - 9];
    out[off] = v;
}

// ---------------- launch ----------------
extern "C" void kernel_launch(void* const* d_in, const int* in_sizes, int n_in,
                              void* d_out, int out_size)
{
    const float* x     = (const float*)d_in[0];
    const float* ln_g  = (const float*)d_in[1];
    const float* ln_b  = (const float*)d_in[2];
    const float* pre_W = (const float*)d_in[3];
    const float* pre_b = (const float*)d_in[4];
    const float* sw_W  = (const float*)d_in[5];
    const float* sw_b  = (const float*)d_in[6];
    const float* W1    = (const float*)d_in[7];
    const float* b1    = (const float*)d_in[8];
    const float* W2    = (const float*)d_in[9];
    const float* b2    = (const float*)d_in[10];
    float* out = (float*)d_out;

    __half *d_W1h, *d_W2h, *d_Wph, *d_Wpl;
    cudaGetSymbolAddress((void**)&d_W1h, g_W1h);
    cudaGetSymbolAddress((void**)&d_W2h, g_W2h);
    cudaGetSymbolAddress((void**)&d_Wph, g_Wph);
    cudaGetSymbolAddress((void**)&d_Wpl, g_Wpl);
    cudaFuncSetAttribute(moe_mma<1>, cudaFuncAttributeMaxDynamicSharedMemorySize, SMEM_MOE);
    cudaFuncSetAttribute(moe_mma<2>, cudaFuncAttributeMaxDynamicSharedMemorySize, SMEM_MOE);
    cudaFuncSetAttribute(pre_mma, cudaFuncAttributeMaxDynamicSharedMemorySize, SMEM_PRE);

    // one-time handles (host-side only; no device memory, work graph unchanged)
    static cudaStream_t s1 = nullptr;
    static cudaEvent_t eFork, eSplit, eW1, eW2, eScan, eTail;
    if (!s1) {
        cudaStreamCreateWithFlags(&s1, cudaStreamNonBlocking);
        cudaEventCreateWithFlags(&eFork,  cudaEventDisableTiming);
        cudaEventCreateWithFlags(&eSplit, cudaEventDisableTiming);
        cudaEventCreateWithFlags(&eW1,    cudaEventDisableTiming);
        cudaEventCreateWithFlags(&eW2,    cudaEventDisableTiming);
        cudaEventCreateWithFlags(&eScan,  cudaEventDisableTiming);
        cudaEventCreateWithFlags(&eTail,  cudaEventDisableTiming);
    }

    const size_t WN4 = (size_t)NEXP * D_MODEL * H_FF / 4;

    // fork: weight prep on s1
    cudaEventRecord(eFork, 0);
    cudaStreamWaitEvent(s1, eFork, 0);
    split_w<<<256, 256, 0, s1>>>(pre_W, d_Wph, d_Wpl, (size_t)D_IN * D_MODEL);
    cudaEventRecord(eSplit, s1);
    convert_w<<<2048, 256, 0, s1>>>(W1, d_W1h, WN4);
    cudaEventRecord(eW1, s1);
    convert_w<<<2048, 256, 0, s1>>>(W2, d_W2h, WN4);
    cudaEventRecord(eW2, s1);

    // main chain
    ln_kernel<<<T_TOK, 256>>>(x, ln_g, ln_b);
    cudaStreamWaitEvent(0, eSplit, 0);
    pre_mma<<<dim3(T_TOK / PBM, D_MODEL / PBN), 256, SMEM_PRE>>>(pre_b);
    router_kernel<<<T_TOK, 256>>>(sw_W, sw_b);
    probsum_kernel<<<NEXP, 256>>>();
    scan_kernel<<<1, 256>>>();
    cudaEventRecord(eScan, 0);
    dispatch_kernel<<<ECAP, 128>>>();

    // tail fork: dropped/extras write disjoint out rows vs moe_mma<2>
    cudaStreamWaitEvent(s1, eScan, 0);
    dropped_kernel<<<T_TOK, 256, 0, s1>>>(out);
    extras_kernel<<<(OUT_EXTRAS_N + 255) / 256, 256, 0, s1>>>(out, out_size);
    cudaEventRecord(eTail, s1);

    cudaStreamWaitEvent(0, eW1, 0);
    moe_mma<1><<<dim3(CAP / BM, H_FF / BN, NEXP), 256, SMEM_MOE>>>(d_W1h, b1, nullptr);
    cudaStreamWaitEvent(0, eW2, 0);
    moe_mma<2><<<dim3(CAP / BM, D_MODEL / BN, NEXP), 256, SMEM_MOE>>>(d_W2h, b2, out);
    cudaStreamWaitEvent(0, eTail, 0);
}